// round 6
// baseline (speedup 1.0000x reference)
#include <cuda_runtime.h>

#define HH 40
#define WW 128
#define PP 5120
#define CC 128
#define KKN 25
#define SPOTN 5
#define NEGV (-1e8f)
#define FMAXV 3.402823466e38f

// ---------------- scratch (device globals; no allocations allowed) ----------
__device__ float g_nimf[PP*CC];
__device__ float g_npcf[PP*CC];
__device__ int   g_nb[PP*KKN];
__device__ unsigned long long g_rowbest[PP];
__device__ unsigned long long g_colbest[PP];
__device__ float g_imbs[PP];   // best_score per pixel
__device__ int   g_imbi[PP];   // best_index per pixel (pc idx)
__device__ float g_pcbs[PP];   // best_pc_score per point
__device__ int   g_pcbi[PP];   // best_pc_idx per point (pixel idx)
__device__ int   g_spot_im[PP*125];
__device__ int   g_spot_pc[PP*125];

__device__ __forceinline__ unsigned f2sort(float f){
    unsigned b = __float_as_uint(f);
    return (b & 0x80000000u) ? ~b : (b | 0x80000000u);
}
__device__ __forceinline__ float sort2f(unsigned u){
    unsigned b = (u & 0x80000000u) ? (u & 0x7fffffffu) : ~u;
    return __uint_as_float(b);
}
__device__ __forceinline__ int iclamp(int v, int lo, int hi){
    return v < lo ? lo : (v > hi ? hi : v);
}
__device__ __forceinline__ unsigned long long maxull(unsigned long long a, unsigned long long b){
    return a > b ? a : b;
}
__device__ __forceinline__ unsigned long long minull(unsigned long long a, unsigned long long b){
    return a < b ? a : b;
}
#define KEYPACK(v,n) ((((unsigned long long)f2sort(v)) << 32) | (unsigned)(~(n)))

// ---------------- K1: L2 normalize both feature sets ------------------------
__global__ __launch_bounds__(256) void k_norm(const float* __restrict__ imf,
                                              const float* __restrict__ pcf){
    int warp = (blockIdx.x*blockDim.x + threadIdx.x) >> 5;
    int lane = threadIdx.x & 31;
    if (warp >= 2*PP) return;
    const float* src = (warp < PP) ? imf : pcf;
    float* dst       = (warp < PP) ? g_nimf : g_npcf;
    int r = (warp < PP) ? warp : warp - PP;
    float4 v = ((const float4*)(src + (size_t)r*CC))[lane];
    float ss = v.x*v.x + v.y*v.y + v.z*v.z + v.w*v.w;
    #pragma unroll
    for (int o=16;o;o>>=1) ss += __shfl_xor_sync(0xffffffffu, ss, o);
    float inv = 1.0f / fmaxf(sqrtf(ss), 1e-12f);
    v.x*=inv; v.y*=inv; v.z*=inv; v.w*=inv;
    ((float4*)(dst + (size_t)r*CC))[lane] = v;
}

// ---------------- K2: init packed argmax accumulators -----------------------
__global__ void k_init(){
    int i = blockIdx.x*blockDim.x + threadIdx.x;
    if (i < PP){ g_rowbest[i] = 0ull; g_colbest[i] = 0ull; }
}

// ---------------- K3: knn (top-25 nearest, self first, tie->lower idx) ------
// 2 rows per block, 128 threads per row (40 KB smem < 48 KB static cap).
// Keys: (d2_bits<<32 | j); min-order == (d2 asc, idx asc) == top_k(-d2) order.
// Extraction order is globally ascending in key, so the owner's rescan just
// excludes key <= last extracted key; smem distances stay read-only after fill.
#define KNN_ROWS 2
#define KNN_TPR  128
__global__ __launch_bounds__(256) void k_knn(const float* __restrict__ pts){
    __shared__ float sd[KNN_ROWS][PP];                 // 40 KB
    __shared__ unsigned long long wmin[KNN_ROWS][4];
    __shared__ unsigned long long best[KNN_ROWS];
    int tid  = threadIdx.x;
    int g    = tid >> 7;          // row within block (0..1)
    int sub  = tid & 127;         // thread within row
    int lane = tid & 31;
    int wig  = (tid >> 5) & 3;    // warp within row group (0..3)
    int i = blockIdx.x*KNN_ROWS + g;
    float px = pts[i*3+0], py = pts[i*3+1], pz = pts[i*3+2];

    unsigned long long lmin = ~0ull;
    for (int j = sub; j < PP; j += KNN_TPR){
        float dx = pts[j*3+0]-px, dy = pts[j*3+1]-py, dz = pts[j*3+2]-pz;
        float d2 = fmaf(dx,dx, fmaf(dy,dy, dz*dz));    // >=0: bit order == numeric
        sd[g][j] = d2;
        unsigned long long key = ((unsigned long long)__float_as_uint(d2) << 32) | (unsigned)j;
        lmin = minull(lmin, key);
    }

    for (int t=0; t<KKN; t++){
        // warp reduce -> 4 warp minima per row -> scalar combine; 2 barriers
        unsigned long long tmp = lmin;
        #pragma unroll
        for (int o=16;o;o>>=1) tmp = minull(tmp, __shfl_xor_sync(0xffffffffu, tmp, o));
        if (lane == 0) wmin[g][wig] = tmp;
        __syncthreads();
        if (sub == 0){
            unsigned long long m = minull(minull(wmin[g][0], wmin[g][1]),
                                          minull(wmin[g][2], wmin[g][3]));
            best[g] = m;
            g_nb[i*KKN + t] = (int)(unsigned)m;
        }
        __syncthreads();
        unsigned long long b = best[g];
        int j = (int)(unsigned)b;
        if ((j & 127) == sub){
            // rescan own stripe (40 elems), excluding already-extracted (key <= b)
            unsigned long long nm = ~0ull;
            #pragma unroll 4
            for (int jj = sub; jj < PP; jj += KNN_TPR){
                unsigned long long key = ((unsigned long long)__float_as_uint(sd[g][jj]) << 32) | (unsigned)jj;
                if (key > b) nm = minull(nm, key);
            }
            lmin = nm;
        }
    }
}

// ---------------- K4: fused GEMM + row/col argmax ----------------------------
// S[p][n] = dot(nimf[p], npcf[n]); row max -> g_rowbest, col max -> g_colbest.
// Accumulators are 16 NAMED float4 registers (no local arrays, no address-of).
#define FOR_ROWS(OP) OP(0,d0a,d0b) OP(1,d1a,d1b) OP(2,d2a,d2b) OP(3,d3a,d3b) \
                     OP(4,d4a,d4b) OP(5,d5a,d5b) OP(6,d6a,d6b) OP(7,d7a,d7b)
#define DECL_ROW(r,A,B) float4 A = {0.f,0.f,0.f,0.f}; float4 B = {0.f,0.f,0.f,0.f};
#define AV0 a0.x
#define AV1 a0.y
#define AV2 a0.z
#define AV3 a0.w
#define AV4 a1.x
#define AV5 a1.y
#define AV6 a1.z
#define AV7 a1.w
#define FMA_ROW(r,A,B) { float av_ = AV##r; \
    A.x = fmaf(av_, b0.x, A.x); A.y = fmaf(av_, b0.y, A.y); \
    A.z = fmaf(av_, b0.z, A.z); A.w = fmaf(av_, b0.w, A.w); \
    B.x = fmaf(av_, b1.x, B.x); B.y = fmaf(av_, b1.y, B.y); \
    B.z = fmaf(av_, b1.z, B.z); B.w = fmaf(av_, b1.w, B.w); }
#define ROW_ST(r,A,B) { int n0_ = c0 + tx*8; \
    unsigned long long bb_ = KEYPACK(A.x, n0_); \
    bb_ = maxull(bb_, KEYPACK(A.y, n0_+1)); bb_ = maxull(bb_, KEYPACK(A.z, n0_+2)); \
    bb_ = maxull(bb_, KEYPACK(A.w, n0_+3)); bb_ = maxull(bb_, KEYPACK(B.x, n0_+4)); \
    bb_ = maxull(bb_, KEYPACK(B.y, n0_+5)); bb_ = maxull(bb_, KEYPACK(B.z, n0_+6)); \
    bb_ = maxull(bb_, KEYPACK(B.w, n0_+7)); \
    red[(ty*8+r)*16 + tx] = bb_; }
#define COL_UPD(r,A,B) { int m_ = r0 + ty*8 + r; \
    e0 = maxull(e0, KEYPACK(A.x, m_)); e1 = maxull(e1, KEYPACK(A.y, m_)); \
    e2 = maxull(e2, KEYPACK(A.z, m_)); e3 = maxull(e3, KEYPACK(A.w, m_)); \
    e4 = maxull(e4, KEYPACK(B.x, m_)); e5 = maxull(e5, KEYPACK(B.y, m_)); \
    e6 = maxull(e6, KEYPACK(B.z, m_)); e7 = maxull(e7, KEYPACK(B.w, m_)); }

__global__ __launch_bounds__(256) void k_gemm(){
    __shared__ __align__(16) char smem_raw[2*32*132*4];  // 33792 B
    float (*As)[132] = (float (*)[132])smem_raw;
    float (*Bs)[132] = (float (*)[132])(smem_raw + 32*132*4);
    int tid = threadIdx.x;
    int tx = tid & 15, ty = tid >> 4;
    int r0 = blockIdx.y*128, c0 = blockIdx.x*128;
    FOR_ROWS(DECL_ROW)

    for (int kc=0; kc<CC; kc+=32){
        #pragma unroll
        for (int it=0; it<4; ++it){
            int idx = it*256 + tid;
            int row = idx >> 3;
            int k4  = (idx & 7)*4;
            float4 a = *(const float4*)&g_nimf[(size_t)(r0+row)*CC + kc + k4];
            As[k4+0][row]=a.x; As[k4+1][row]=a.y; As[k4+2][row]=a.z; As[k4+3][row]=a.w;
            float4 b = *(const float4*)&g_npcf[(size_t)(c0+row)*CC + kc + k4];
            Bs[k4+0][row]=b.x; Bs[k4+1][row]=b.y; Bs[k4+2][row]=b.z; Bs[k4+3][row]=b.w;
        }
        __syncthreads();
        #pragma unroll 8
        for (int k=0; k<32; k++){
            float4 a0 = *(const float4*)&As[k][ty*8+0];
            float4 a1 = *(const float4*)&As[k][ty*8+4];
            float4 b0 = *(const float4*)&Bs[k][tx*8+0];
            float4 b1 = *(const float4*)&Bs[k][tx*8+4];
            FOR_ROWS(FMA_ROW)
        }
        __syncthreads();
    }

    unsigned long long* red = (unsigned long long*)smem_raw;  // 2048 entries
    // ---- row argmax (index = point n, tie -> lower n) ----
    FOR_ROWS(ROW_ST)
    __syncthreads();
    if (tid < 128){
        unsigned long long b = 0ull;
        #pragma unroll
        for (int t=0;t<16;t++) b = maxull(b, red[tid*16+t]);
        atomicMax(&g_rowbest[r0+tid], b);
    }
    __syncthreads();
    // ---- col argmax (index = pixel p, tie -> lower p) ----
    unsigned long long e0=0,e1=0,e2=0,e3=0,e4=0,e5=0,e6=0,e7=0;
    FOR_ROWS(COL_UPD)
    red[(tx*8+0)*16 + ty] = e0;
    red[(tx*8+1)*16 + ty] = e1;
    red[(tx*8+2)*16 + ty] = e2;
    red[(tx*8+3)*16 + ty] = e3;
    red[(tx*8+4)*16 + ty] = e4;
    red[(tx*8+5)*16 + ty] = e5;
    red[(tx*8+6)*16 + ty] = e6;
    red[(tx*8+7)*16 + ty] = e7;
    __syncthreads();
    if (tid < 128){
        unsigned long long b = 0ull;
        #pragma unroll
        for (int t=0;t<16;t++) b = maxull(b, red[tid*16+t]);
        atomicMax(&g_colbest[c0+tid], b);
    }
}

// ---------------- K5: unpack packed argmax ----------------------------------
__global__ void k_unpack(){
    int i = blockIdx.x*blockDim.x + threadIdx.x;
    if (i >= PP) return;
    unsigned long long k1 = g_rowbest[i];
    g_imbs[i] = sort2f((unsigned)(k1 >> 32));
    g_imbi[i] = (int)(~(unsigned)k1);
    unsigned long long k2 = g_colbest[i];
    g_pcbs[i] = sort2f((unsigned)(k2 >> 32));
    g_pcbi[i] = (int)(~(unsigned)k2);
}

// ---------------- K6: im branch: sims, softmax, select out, top-4, spot -----
__global__ __launch_bounds__(128) void k_impix(float* __restrict__ sel_out){
    int warp = (blockIdx.x*blockDim.x + threadIdx.x) >> 5;
    int lane = threadIdx.x & 31;
    if (warp >= PP) return;
    int p = warp, h = p >> 7, w = p & 127;   // WW == 128
    float4 cf = ((const float4*)(g_nimf + (size_t)p*CC))[lane];

    float myval = 0.f;
    #pragma unroll 1
    for (int k=0; k<KKN; k++){
        int di = k/5 - 2, dj = k%5 - 2;
        int hh = iclamp(h+di, 0, HH-1), ww = iclamp(w+dj, 0, WW-1);
        float4 nf = ((const float4*)(g_nimf + (size_t)(hh*WW+ww)*CC))[lane];
        float s = cf.x*nf.x + cf.y*nf.y + cf.z*nf.z + cf.w*nf.w;
        #pragma unroll
        for (int o=16;o;o>>=1) s += __shfl_xor_sync(0xffffffffu, s, o);
        if (lane == k) myval = s;
    }
    // softmax over lanes 0..24
    float v = (lane < KKN) ? myval : -FMAXV;
    float m = v;
    #pragma unroll
    for (int o=16;o;o>>=1) m = fmaxf(m, __shfl_xor_sync(0xffffffffu, m, o));
    float e = (lane < KKN) ? expf(v - m) : 0.f;
    float su = e;
    #pragma unroll
    for (int o=16;o;o>>=1) su += __shfl_xor_sync(0xffffffffu, su, o);
    float soft = e / su;

    int di = lane/5 - 2, dj = lane%5 - 2;
    float selv = NEGV;
    if (lane < KKN){
        bool inb = ((unsigned)(h+di) < (unsigned)HH) && ((unsigned)(w+dj) < (unsigned)WW);
        int hh = iclamp(h+di, 0, HH-1), ww = iclamp(w+dj, 0, WW-1);
        float conf = g_imbs[hh*WW+ww];
        selv = inb ? soft*conf : NEGV;
        sel_out[(size_t)lane*PP + p] = selv;
    }
    // seeding: center (k=12) then top-4 excluding center; process immediately
    float cand = (lane < KKN && lane != 12) ? selv : -FMAXV;
    #pragma unroll 1
    for (int s=0; s<SPOTN; s++){
        int kk;
        if (s == 0){
            kk = 12;
        } else {
            unsigned long long key = ((unsigned long long)f2sort(cand) << 32) | (unsigned)(31 - lane);
            #pragma unroll
            for (int o=16;o;o>>=1){
                unsigned long long ok = __shfl_xor_sync(0xffffffffu, key, o);
                if (ok > key) key = ok;
            }
            kk = 31 - (int)(key & 0xffffffffull);
            if (lane == kk) cand = -FMAXV;
        }
        int q = (h + kk/5 - 2)*WW + (w + kk%5 - 2);  // selected are always in-bounds
        int sd = g_imbi[q];
        if (lane < KKN) g_spot_im[(size_t)p*125 + s*25 + lane] = g_nb[sd*KKN + lane];
    }
}

// ---------------- K7: pc branch ---------------------------------------------
__global__ __launch_bounds__(128) void k_pcpoint(){
    int warp = (blockIdx.x*blockDim.x + threadIdx.x) >> 5;
    int lane = threadIdx.x & 31;
    if (warp >= PP) return;
    int p = warp;
    float4 cf = ((const float4*)(g_npcf + (size_t)p*CC))[lane];

    float myval = 0.f; int myq = 0;
    #pragma unroll 1
    for (int k=0; k<KKN; k++){
        int q = g_nb[p*KKN + k];
        float4 nf = ((const float4*)(g_npcf + (size_t)q*CC))[lane];
        float s = cf.x*nf.x + cf.y*nf.y + cf.z*nf.z + cf.w*nf.w;
        #pragma unroll
        for (int o=16;o;o>>=1) s += __shfl_xor_sync(0xffffffffu, s, o);
        if (lane == k){ myval = s; myq = q; }
    }
    float v = (lane < KKN) ? myval : -FMAXV;
    float m = v;
    #pragma unroll
    for (int o=16;o;o>>=1) m = fmaxf(m, __shfl_xor_sync(0xffffffffu, m, o));
    float e = (lane < KKN) ? expf(v - m) : 0.f;
    float su = e;
    #pragma unroll
    for (int o=16;o;o>>=1) su += __shfl_xor_sync(0xffffffffu, su, o);
    float soft = e / su;

    float selv = NEGV;
    if (lane < KKN) selv = (lane == 0) ? NEGV : soft * g_pcbs[myq];
    float cand = (lane >= 1 && lane < KKN) ? selv : -FMAXV;
    #pragma unroll 1
    for (int s=0; s<SPOTN; s++){
        int kk;
        if (s == 0){
            kk = 0;
        } else {
            unsigned long long key = ((unsigned long long)f2sort(cand) << 32) | (unsigned)(31 - lane);
            #pragma unroll
            for (int o=16;o;o>>=1){
                unsigned long long ok = __shfl_xor_sync(0xffffffffu, key, o);
                if (ok > key) key = ok;
            }
            kk = 31 - (int)(key & 0xffffffffull);
            if (lane == kk) cand = -FMAXV;
        }
        int qq = __shfl_sync(0xffffffffu, myq, kk);
        int pix = g_pcbi[qq];
        int pr = pix >> 7, pc = pix & 127;
        if (lane < KKN){
            int rr = iclamp(pr + lane/5 - 2, 0, HH-1);
            int cc = iclamp(pc + lane%5 - 2, 0, WW-1);
            g_spot_pc[(size_t)p*125 + s*25 + lane] = rr*WW + cc;
        }
    }
}

// ---------------- K8: scatter mask + stable top-125 (bitmask scan) ----------
// which: 0 -> g_spot_im, 1 -> g_spot_pc (device-global pointers bound in-kernel)
__global__ __launch_bounds__(256) void k_mask(int which,
                                              float* __restrict__ omask,
                                              float* __restrict__ oidx){
    __shared__ unsigned bm[32][160];   // 32 rows x 5120 bits
    const int* spot = which ? g_spot_pc : g_spot_im;
    int r0 = blockIdx.x*32;
    int tid = threadIdx.x;
    for (int i=tid; i<32*160; i+=256) ((unsigned*)bm)[i] = 0u;
    __syncthreads();
    for (int e=tid; e<32*125; e+=256){
        int row = e / 125;
        int v = spot[(size_t)(r0+row)*125 + (e % 125)];
        atomicOr(&bm[row][v>>5], 1u << (v & 31));
    }
    __syncthreads();
    if (tid < 32){
        int row = tid, t = 0;
        float* om = omask + (size_t)(r0+row)*125;
        float* oi = oidx  + (size_t)(r0+row)*125;
        for (int w2=0; w2<160; w2++){
            unsigned x = bm[row][w2];
            while (x){
                int b = __ffs(x) - 1; x &= x - 1;
                oi[t] = (float)(w2*32 + b); om[t] = 1.f; t++;
            }
        }
        for (int j=0; t<125; j++){
            if (!((bm[row][j>>5] >> (j&31)) & 1u)){
                oi[t] = (float)j; om[t] = 0.f; t++;
            }
        }
    }
}

// ---------------- launch ------------------------------------------------------
extern "C" void kernel_launch(void* const* d_in, const int* in_sizes, int n_in,
                              void* d_out, int out_size){
    const float* imf = (const float*)d_in[0];
    const float* pcf = (const float*)d_in[1];
    const float* pts = (const float*)d_in[2];
    float* out = (float*)d_out;

    float* sel_out     = out;                       // 25*5120
    float* mask_out    = out + 25*PP;               // 5120*125
    float* idx_out     = out + 25*PP + 125*PP;      // 5120*125
    float* idx_pc_out  = out + 25*PP + 2*125*PP;    // 5120*125
    float* mask_pc_out = out + 25*PP + 3*125*PP;    // 5120*125

    k_norm<<<(2*PP*32 + 255)/256, 256>>>(imf, pcf);
    k_init<<<(PP+255)/256, 256>>>();
    k_knn<<<PP/KNN_ROWS, 256>>>(pts);
    dim3 gg(PP/128, PP/128);
    k_gemm<<<gg, 256>>>();
    k_unpack<<<(PP+255)/256, 256>>>();
    k_impix<<<PP/4, 128>>>(sel_out);
    k_pcpoint<<<PP/4, 128>>>();
    k_mask<<<PP/32, 256>>>(0, mask_out, idx_out);
    k_mask<<<PP/32, 256>>>(1, mask_pc_out, idx_pc_out);
}

// round 7
// speedup vs baseline: 1.0439x; 1.0439x over previous
#include <cuda_runtime.h>

#define HH 40
#define WW 128
#define PP 5120
#define CC 128
#define KKN 25
#define SPOTN 5
#define NEGV (-1e8f)
#define FMAXV 3.402823466e38f

// ---------------- scratch (device globals; no allocations allowed) ----------
__device__ float g_nimf[PP*CC];
__device__ float g_npcf[PP*CC];
__device__ float g_ahi[PP*CC];   // tf32 hi/lo splits of normalized imf
__device__ float g_alo[PP*CC];
__device__ float g_bhi[PP*CC];   // tf32 hi/lo splits of normalized pcf
__device__ float g_blo[PP*CC];
__device__ int   g_nb[PP*KKN];
__device__ unsigned long long g_rowbest[PP];
__device__ unsigned long long g_colbest[PP];
__device__ float g_imbs[PP];   // best_score per pixel
__device__ int   g_imbi[PP];   // best_index per pixel (pc idx)
__device__ float g_pcbs[PP];   // best_pc_score per point
__device__ int   g_pcbi[PP];   // best_pc_idx per point (pixel idx)
__device__ int   g_spot_im[PP*125];
__device__ int   g_spot_pc[PP*125];

__device__ __forceinline__ unsigned f2sort(float f){
    unsigned b = __float_as_uint(f);
    return (b & 0x80000000u) ? ~b : (b | 0x80000000u);
}
__device__ __forceinline__ float sort2f(unsigned u){
    unsigned b = (u & 0x80000000u) ? (u & 0x7fffffffu) : ~u;
    return __uint_as_float(b);
}
__device__ __forceinline__ int iclamp(int v, int lo, int hi){
    return v < lo ? lo : (v > hi ? hi : v);
}
__device__ __forceinline__ unsigned long long maxull(unsigned long long a, unsigned long long b){
    return a > b ? a : b;
}
__device__ __forceinline__ unsigned long long minull(unsigned long long a, unsigned long long b){
    return a < b ? a : b;
}
__device__ __forceinline__ float tf32r(float x){
    unsigned u; asm("cvt.rna.tf32.f32 %0, %1;" : "=r"(u) : "f"(x));
    return __uint_as_float(u);
}
#define KEYPACK(v,n) ((((unsigned long long)f2sort(v)) << 32) | (unsigned)(~(n)))

// ---------------- K1: L2 normalize + tf32 hi/lo split + argmax init ---------
__global__ __launch_bounds__(256) void k_norm(const float* __restrict__ imf,
                                              const float* __restrict__ pcf){
    int gt = blockIdx.x*blockDim.x + threadIdx.x;
    if (gt < PP){ g_rowbest[gt] = 0ull; g_colbest[gt] = 0ull; }
    int warp = gt >> 5;
    int lane = threadIdx.x & 31;
    if (warp >= 2*PP) return;
    const float* src = (warp < PP) ? imf : pcf;
    float* dst       = (warp < PP) ? g_nimf : g_npcf;
    float* dhi       = (warp < PP) ? g_ahi : g_bhi;
    float* dlo       = (warp < PP) ? g_alo : g_blo;
    int r = (warp < PP) ? warp : warp - PP;
    float4 v = ((const float4*)(src + (size_t)r*CC))[lane];
    float ss = v.x*v.x + v.y*v.y + v.z*v.z + v.w*v.w;
    #pragma unroll
    for (int o=16;o;o>>=1) ss += __shfl_xor_sync(0xffffffffu, ss, o);
    float inv = 1.0f / fmaxf(sqrtf(ss), 1e-12f);
    v.x*=inv; v.y*=inv; v.z*=inv; v.w*=inv;
    ((float4*)(dst + (size_t)r*CC))[lane] = v;
    float4 hi, lo;
    hi.x = tf32r(v.x); lo.x = tf32r(v.x - hi.x);
    hi.y = tf32r(v.y); lo.y = tf32r(v.y - hi.y);
    hi.z = tf32r(v.z); lo.z = tf32r(v.z - hi.z);
    hi.w = tf32r(v.w); lo.w = tf32r(v.w - hi.w);
    ((float4*)(dhi + (size_t)r*CC))[lane] = hi;
    ((float4*)(dlo + (size_t)r*CC))[lane] = lo;
}

// ---------------- K3: knn (top-25 nearest, self first, tie->lower idx) ------
#define KNN_ROWS 2
#define KNN_TPR  128
__global__ __launch_bounds__(256) void k_knn(const float* __restrict__ pts){
    __shared__ float sd[KNN_ROWS][PP];                 // 40 KB
    __shared__ unsigned long long wmin[KNN_ROWS][4];
    __shared__ unsigned long long best[KNN_ROWS];
    int tid  = threadIdx.x;
    int g    = tid >> 7;
    int sub  = tid & 127;
    int lane = tid & 31;
    int wig  = (tid >> 5) & 3;
    int i = blockIdx.x*KNN_ROWS + g;
    float px = pts[i*3+0], py = pts[i*3+1], pz = pts[i*3+2];

    unsigned long long lmin = ~0ull;
    for (int j = sub; j < PP; j += KNN_TPR){
        float dx = pts[j*3+0]-px, dy = pts[j*3+1]-py, dz = pts[j*3+2]-pz;
        float d2 = fmaf(dx,dx, fmaf(dy,dy, dz*dz));
        sd[g][j] = d2;
        unsigned long long key = ((unsigned long long)__float_as_uint(d2) << 32) | (unsigned)j;
        lmin = minull(lmin, key);
    }

    for (int t=0; t<KKN; t++){
        unsigned long long tmp = lmin;
        #pragma unroll
        for (int o=16;o;o>>=1) tmp = minull(tmp, __shfl_xor_sync(0xffffffffu, tmp, o));
        if (lane == 0) wmin[g][wig] = tmp;
        __syncthreads();
        if (sub == 0){
            unsigned long long m = minull(minull(wmin[g][0], wmin[g][1]),
                                          minull(wmin[g][2], wmin[g][3]));
            best[g] = m;
            g_nb[i*KKN + t] = (int)(unsigned)m;
        }
        __syncthreads();
        unsigned long long b = best[g];
        int j = (int)(unsigned)b;
        if ((j & 127) == sub){
            unsigned long long nm = ~0ull;
            #pragma unroll 4
            for (int jj = sub; jj < PP; jj += KNN_TPR){
                unsigned long long key = ((unsigned long long)__float_as_uint(sd[g][jj]) << 32) | (unsigned)jj;
                if (key > b) nm = minull(nm, key);
            }
            lmin = nm;
        }
    }
}

// ---------------- K4: 3xTF32 tensor-core GEMM + row/col argmax ---------------
// S = nimf @ npcf^T computed as Ahi·Bhi + Ahi·Blo + Alo·Bhi (tf32 mma, fp32 acc).
// Block 128x128, 8 warps of 64x32 (m16n8k8 tiles). smem [m][k] pad 36: staging
// STS.128 and fragment LDS.32 both bank-conflict-free.
__device__ __forceinline__ void mma_tf32(float& d0, float& d1, float& d2, float& d3,
    unsigned a0, unsigned a1, unsigned a2, unsigned a3, unsigned b0, unsigned b1){
    asm volatile("mma.sync.aligned.m16n8k8.row.col.f32.tf32.tf32.f32 "
        "{%0,%1,%2,%3},{%4,%5,%6,%7},{%8,%9},{%0,%1,%2,%3};\n"
        : "+f"(d0),"+f"(d1),"+f"(d2),"+f"(d3)
        : "r"(a0),"r"(a1),"r"(a2),"r"(a3),"r"(b0),"r"(b1));
}

__global__ __launch_bounds__(256,2) void k_gemm(){
    __shared__ __align__(16) float As[128][36];
    __shared__ __align__(16) float Bs[128][36];
    int tid = threadIdx.x;
    int lane = tid & 31;
    int warp = tid >> 5;
    int wm = warp >> 2, wn = warp & 3;
    int g = lane >> 2, q = lane & 3;
    int r0 = blockIdx.y*128, c0 = blockIdx.x*128;
    int mb = wm*64, nb = wn*32;

    float acc[4][4][4];
    #pragma unroll
    for (int a=0;a<4;a++)
        #pragma unroll
        for (int b=0;b<4;b++)
            #pragma unroll
            for (int i2=0;i2<4;i2++) acc[a][b][i2] = 0.f;

    #pragma unroll 1
    for (int c=0;c<12;c++){
        const float* Ap = (c < 8) ? g_ahi : g_alo;             // hi,hi,lo
        const float* Bp = (c >= 4 && c < 8) ? g_blo : g_bhi;   // hi,lo,hi
        int k0 = (c & 3)*32;
        #pragma unroll
        for (int it=0; it<4; it++){
            int idx = it*256 + tid;
            int row = idx >> 3;
            int kk  = (idx & 7)*4;
            *(float4*)&As[row][kk] = *(const float4*)&Ap[(size_t)(r0+row)*CC + k0 + kk];
            *(float4*)&Bs[row][kk] = *(const float4*)&Bp[(size_t)(c0+row)*CC + k0 + kk];
        }
        __syncthreads();
        #pragma unroll
        for (int ks=0; ks<4; ks++){
            int kq = ks*8 + q;
            unsigned af[4][4], bf[4][2];
            #pragma unroll
            for (int t=0;t<4;t++){
                int m0 = mb + t*16 + g;
                af[t][0] = __float_as_uint(As[m0  ][kq  ]);
                af[t][1] = __float_as_uint(As[m0+8][kq  ]);
                af[t][2] = __float_as_uint(As[m0  ][kq+4]);
                af[t][3] = __float_as_uint(As[m0+8][kq+4]);
                int n0 = nb + t*8 + g;
                bf[t][0] = __float_as_uint(Bs[n0][kq  ]);
                bf[t][1] = __float_as_uint(Bs[n0][kq+4]);
            }
            #pragma unroll
            for (int tm=0; tm<4; tm++)
                #pragma unroll
                for (int tn=0; tn<4; tn++)
                    mma_tf32(acc[tm][tn][0], acc[tm][tn][1], acc[tm][tn][2], acc[tm][tn][3],
                             af[tm][0], af[tm][1], af[tm][2], af[tm][3],
                             bf[tn][0], bf[tn][1]);
        }
        __syncthreads();
    }

    // ---- epilogue: packed row/col argmax via shared u64 atomics ----
    unsigned long long* rowk = (unsigned long long*)&As[0][0];   // 128
    unsigned long long* colk = rowk + 128;                       // 128
    if (tid < 128){ rowk[tid] = 0ull; colk[tid] = 0ull; }
    __syncthreads();

    #pragma unroll
    for (int tm=0; tm<4; tm++){
        unsigned long long klo = 0ull, khi = 0ull;
        #pragma unroll
        for (int tn=0; tn<4; tn++){
            int n0 = c0 + nb + tn*8 + 2*q;
            klo = maxull(klo, KEYPACK(acc[tm][tn][0], n0));
            klo = maxull(klo, KEYPACK(acc[tm][tn][1], n0+1));
            khi = maxull(khi, KEYPACK(acc[tm][tn][2], n0));
            khi = maxull(khi, KEYPACK(acc[tm][tn][3], n0+1));
        }
        atomicMax(&rowk[mb + tm*16 + g    ], klo);
        atomicMax(&rowk[mb + tm*16 + g + 8], khi);
    }
    #pragma unroll
    for (int tn=0; tn<4; tn++){
        unsigned long long c0k = 0ull, c1k = 0ull;
        #pragma unroll
        for (int tm=0; tm<4; tm++){
            int m0 = r0 + mb + tm*16 + g;
            c0k = maxull(c0k, KEYPACK(acc[tm][tn][0], m0));
            c0k = maxull(c0k, KEYPACK(acc[tm][tn][2], m0+8));
            c1k = maxull(c1k, KEYPACK(acc[tm][tn][1], m0));
            c1k = maxull(c1k, KEYPACK(acc[tm][tn][3], m0+8));
        }
        atomicMax(&colk[nb + tn*8 + 2*q    ], c0k);
        atomicMax(&colk[nb + tn*8 + 2*q + 1], c1k);
    }
    __syncthreads();
    if (tid < 128) atomicMax(&g_rowbest[r0+tid], rowk[tid]);
    else           atomicMax(&g_colbest[c0+tid-128], colk[tid-128]);
}

// ---------------- K5: unpack packed argmax ----------------------------------
__global__ void k_unpack(){
    int i = blockIdx.x*blockDim.x + threadIdx.x;
    if (i >= PP) return;
    unsigned long long k1 = g_rowbest[i];
    g_imbs[i] = sort2f((unsigned)(k1 >> 32));
    g_imbi[i] = (int)(~(unsigned)k1);
    unsigned long long k2 = g_colbest[i];
    g_pcbs[i] = sort2f((unsigned)(k2 >> 32));
    g_pcbi[i] = (int)(~(unsigned)k2);
}

// ---------------- K6: im branch: sims, softmax, select out, top-4, spot -----
__global__ __launch_bounds__(128) void k_impix(float* __restrict__ sel_out){
    int warp = (blockIdx.x*blockDim.x + threadIdx.x) >> 5;
    int lane = threadIdx.x & 31;
    if (warp >= PP) return;
    int p = warp, h = p >> 7, w = p & 127;   // WW == 128
    float4 cf = ((const float4*)(g_nimf + (size_t)p*CC))[lane];

    float myval = 0.f;
    #pragma unroll 1
    for (int k=0; k<KKN; k++){
        int di = k/5 - 2, dj = k%5 - 2;
        int hh = iclamp(h+di, 0, HH-1), ww = iclamp(w+dj, 0, WW-1);
        float4 nf = ((const float4*)(g_nimf + (size_t)(hh*WW+ww)*CC))[lane];
        float s = cf.x*nf.x + cf.y*nf.y + cf.z*nf.z + cf.w*nf.w;
        #pragma unroll
        for (int o=16;o;o>>=1) s += __shfl_xor_sync(0xffffffffu, s, o);
        if (lane == k) myval = s;
    }
    float v = (lane < KKN) ? myval : -FMAXV;
    float m = v;
    #pragma unroll
    for (int o=16;o;o>>=1) m = fmaxf(m, __shfl_xor_sync(0xffffffffu, m, o));
    float e = (lane < KKN) ? expf(v - m) : 0.f;
    float su = e;
    #pragma unroll
    for (int o=16;o;o>>=1) su += __shfl_xor_sync(0xffffffffu, su, o);
    float soft = e / su;

    int di = lane/5 - 2, dj = lane%5 - 2;
    float selv = NEGV;
    if (lane < KKN){
        bool inb = ((unsigned)(h+di) < (unsigned)HH) && ((unsigned)(w+dj) < (unsigned)WW);
        int hh = iclamp(h+di, 0, HH-1), ww = iclamp(w+dj, 0, WW-1);
        float conf = g_imbs[hh*WW+ww];
        selv = inb ? soft*conf : NEGV;
        sel_out[(size_t)lane*PP + p] = selv;
    }
    float cand = (lane < KKN && lane != 12) ? selv : -FMAXV;
    #pragma unroll 1
    for (int s=0; s<SPOTN; s++){
        int kk;
        if (s == 0){
            kk = 12;
        } else {
            unsigned long long key = ((unsigned long long)f2sort(cand) << 32) | (unsigned)(31 - lane);
            #pragma unroll
            for (int o=16;o;o>>=1){
                unsigned long long ok = __shfl_xor_sync(0xffffffffu, key, o);
                if (ok > key) key = ok;
            }
            kk = 31 - (int)(key & 0xffffffffull);
            if (lane == kk) cand = -FMAXV;
        }
        int q = (h + kk/5 - 2)*WW + (w + kk%5 - 2);
        int sd = g_imbi[q];
        if (lane < KKN) g_spot_im[(size_t)p*125 + s*25 + lane] = g_nb[sd*KKN + lane];
    }
}

// ---------------- K7: pc branch ---------------------------------------------
__global__ __launch_bounds__(128) void k_pcpoint(){
    int warp = (blockIdx.x*blockDim.x + threadIdx.x) >> 5;
    int lane = threadIdx.x & 31;
    if (warp >= PP) return;
    int p = warp;
    float4 cf = ((const float4*)(g_npcf + (size_t)p*CC))[lane];

    float myval = 0.f; int myq = 0;
    #pragma unroll 1
    for (int k=0; k<KKN; k++){
        int q = g_nb[p*KKN + k];
        float4 nf = ((const float4*)(g_npcf + (size_t)q*CC))[lane];
        float s = cf.x*nf.x + cf.y*nf.y + cf.z*nf.z + cf.w*nf.w;
        #pragma unroll
        for (int o=16;o;o>>=1) s += __shfl_xor_sync(0xffffffffu, s, o);
        if (lane == k){ myval = s; myq = q; }
    }
    float v = (lane < KKN) ? myval : -FMAXV;
    float m = v;
    #pragma unroll
    for (int o=16;o;o>>=1) m = fmaxf(m, __shfl_xor_sync(0xffffffffu, m, o));
    float e = (lane < KKN) ? expf(v - m) : 0.f;
    float su = e;
    #pragma unroll
    for (int o=16;o;o>>=1) su += __shfl_xor_sync(0xffffffffu, su, o);
    float soft = e / su;

    float selv = NEGV;
    if (lane < KKN) selv = (lane == 0) ? NEGV : soft * g_pcbs[myq];
    float cand = (lane >= 1 && lane < KKN) ? selv : -FMAXV;
    #pragma unroll 1
    for (int s=0; s<SPOTN; s++){
        int kk;
        if (s == 0){
            kk = 0;
        } else {
            unsigned long long key = ((unsigned long long)f2sort(cand) << 32) | (unsigned)(31 - lane);
            #pragma unroll
            for (int o=16;o;o>>=1){
                unsigned long long ok = __shfl_xor_sync(0xffffffffu, key, o);
                if (ok > key) key = ok;
            }
            kk = 31 - (int)(key & 0xffffffffull);
            if (lane == kk) cand = -FMAXV;
        }
        int qq = __shfl_sync(0xffffffffu, myq, kk);
        int pix = g_pcbi[qq];
        int pr = pix >> 7, pc = pix & 127;
        if (lane < KKN){
            int rr = iclamp(pr + lane/5 - 2, 0, HH-1);
            int cc = iclamp(pc + lane%5 - 2, 0, WW-1);
            g_spot_pc[(size_t)p*125 + s*25 + lane] = rr*WW + cc;
        }
    }
}

// ---------------- K8: scatter mask + stable top-125 (bitmask scan) ----------
__global__ __launch_bounds__(256) void k_mask(int which,
                                              float* __restrict__ omask,
                                              float* __restrict__ oidx){
    __shared__ unsigned bm[32][160];
    const int* spot = which ? g_spot_pc : g_spot_im;
    int r0 = blockIdx.x*32;
    int tid = threadIdx.x;
    for (int i=tid; i<32*160; i+=256) ((unsigned*)bm)[i] = 0u;
    __syncthreads();
    for (int e=tid; e<32*125; e+=256){
        int row = e / 125;
        int v = spot[(size_t)(r0+row)*125 + (e % 125)];
        atomicOr(&bm[row][v>>5], 1u << (v & 31));
    }
    __syncthreads();
    if (tid < 32){
        int row = tid, t = 0;
        float* om = omask + (size_t)(r0+row)*125;
        float* oi = oidx  + (size_t)(r0+row)*125;
        for (int w2=0; w2<160; w2++){
            unsigned x = bm[row][w2];
            while (x){
                int b = __ffs(x) - 1; x &= x - 1;
                oi[t] = (float)(w2*32 + b); om[t] = 1.f; t++;
            }
        }
        for (int j=0; t<125; j++){
            if (!((bm[row][j>>5] >> (j&31)) & 1u)){
                oi[t] = (float)j; om[t] = 0.f; t++;
            }
        }
    }
}

// ---------------- launch ------------------------------------------------------
extern "C" void kernel_launch(void* const* d_in, const int* in_sizes, int n_in,
                              void* d_out, int out_size){
    const float* imf = (const float*)d_in[0];
    const float* pcf = (const float*)d_in[1];
    const float* pts = (const float*)d_in[2];
    float* out = (float*)d_out;

    float* sel_out     = out;                       // 25*5120
    float* mask_out    = out + 25*PP;               // 5120*125
    float* idx_out     = out + 25*PP + 125*PP;      // 5120*125
    float* idx_pc_out  = out + 25*PP + 2*125*PP;    // 5120*125
    float* mask_pc_out = out + 25*PP + 3*125*PP;    // 5120*125

    k_norm<<<(2*PP*32 + 255)/256, 256>>>(imf, pcf);
    k_knn<<<PP/KNN_ROWS, 256>>>(pts);
    k_gemm<<<dim3(PP/128, PP/128), 256>>>();
    k_unpack<<<(PP+255)/256, 256>>>();
    k_impix<<<PP/4, 128>>>(sel_out);
    k_pcpoint<<<PP/4, 128>>>();
    k_mask<<<PP/32, 256>>>(0, mask_out, idx_out);
    k_mask<<<PP/32, 256>>>(1, mask_pc_out, idx_pc_out);
}

// round 8
// speedup vs baseline: 1.0446x; 1.0007x over previous
#include <cuda_runtime.h>

#define HH 40
#define WW 128
#define PP 5120
#define CC 128
#define KKN 25
#define SPOTN 5
#define NEGV (-1e8f)
#define FMAXV 3.402823466e38f

// ---------------- scratch (device globals; no allocations allowed) ----------
__device__ float g_nimf[PP*CC];
__device__ float g_npcf[PP*CC];
__device__ float g_ahi[PP*CC];   // tf32 hi/lo splits of normalized imf
__device__ float g_alo[PP*CC];
__device__ float g_bhi[PP*CC];   // tf32 hi/lo splits of normalized pcf
__device__ float g_blo[PP*CC];
__device__ int   g_nb[PP*KKN];
__device__ unsigned long long g_rowbest[PP];
__device__ unsigned long long g_colbest[PP];
__device__ float g_imbs[PP];   // best_score per pixel
__device__ int   g_imbi[PP];   // best_index per pixel (pc idx)
__device__ float g_pcbs[PP];   // best_pc_score per point
__device__ int   g_pcbi[PP];   // best_pc_idx per point (pixel idx)
__device__ int   g_spot_im[PP*125];
__device__ int   g_spot_pc[PP*125];

__device__ __forceinline__ unsigned f2sort(float f){
    unsigned b = __float_as_uint(f);
    return (b & 0x80000000u) ? ~b : (b | 0x80000000u);
}
__device__ __forceinline__ float sort2f(unsigned u){
    unsigned b = (u & 0x80000000u) ? (u & 0x7fffffffu) : ~u;
    return __uint_as_float(b);
}
__device__ __forceinline__ int iclamp(int v, int lo, int hi){
    return v < lo ? lo : (v > hi ? hi : v);
}
__device__ __forceinline__ unsigned long long maxull(unsigned long long a, unsigned long long b){
    return a > b ? a : b;
}
__device__ __forceinline__ unsigned long long minull(unsigned long long a, unsigned long long b){
    return a < b ? a : b;
}
__device__ __forceinline__ float tf32r(float x){
    unsigned u; asm("cvt.rna.tf32.f32 %0, %1;" : "=r"(u) : "f"(x));
    return __uint_as_float(u);
}
#define KEYPACK(v,n) ((((unsigned long long)f2sort(v)) << 32) | (unsigned)(~(n)))

// ---------------- K1a/K1b: L2 normalize + tf32 hi/lo split ------------------
// which==0: imf -> nimf/ahi/alo (+ argmax accumulator init); which==1: pcf.
__global__ __launch_bounds__(256) void k_norm(const float* __restrict__ src,
                                              int which){
    int gt = blockIdx.x*blockDim.x + threadIdx.x;
    if (!which && gt < PP){ g_rowbest[gt] = 0ull; g_colbest[gt] = 0ull; }
    int r = gt >> 5;
    int lane = threadIdx.x & 31;
    if (r >= PP) return;
    float* dst = which ? g_npcf : g_nimf;
    float* dhi = which ? g_bhi : g_ahi;
    float* dlo = which ? g_blo : g_alo;
    float4 v = ((const float4*)(src + (size_t)r*CC))[lane];
    float ss = v.x*v.x + v.y*v.y + v.z*v.z + v.w*v.w;
    #pragma unroll
    for (int o=16;o;o>>=1) ss += __shfl_xor_sync(0xffffffffu, ss, o);
    float inv = 1.0f / fmaxf(sqrtf(ss), 1e-12f);
    v.x*=inv; v.y*=inv; v.z*=inv; v.w*=inv;
    ((float4*)(dst + (size_t)r*CC))[lane] = v;
    float4 hi, lo;
    hi.x = tf32r(v.x); lo.x = tf32r(v.x - hi.x);
    hi.y = tf32r(v.y); lo.y = tf32r(v.y - hi.y);
    hi.z = tf32r(v.z); lo.z = tf32r(v.z - hi.z);
    hi.w = tf32r(v.w); lo.w = tf32r(v.w - hi.w);
    ((float4*)(dhi + (size_t)r*CC))[lane] = hi;
    ((float4*)(dlo + (size_t)r*CC))[lane] = lo;
}

// ---------------- K3: knn (top-25 nearest, self first, tie->lower idx) ------
#define KNN_ROWS 2
#define KNN_TPR  128
__global__ __launch_bounds__(256) void k_knn(const float* __restrict__ pts){
    __shared__ float sd[KNN_ROWS][PP];                 // 40 KB
    __shared__ unsigned long long wmin[KNN_ROWS][4];
    __shared__ unsigned long long best[KNN_ROWS];
    int tid  = threadIdx.x;
    int g    = tid >> 7;
    int sub  = tid & 127;
    int lane = tid & 31;
    int wig  = (tid >> 5) & 3;
    int i = blockIdx.x*KNN_ROWS + g;
    float px = pts[i*3+0], py = pts[i*3+1], pz = pts[i*3+2];

    unsigned long long lmin = ~0ull;
    for (int j = sub; j < PP; j += KNN_TPR){
        float dx = pts[j*3+0]-px, dy = pts[j*3+1]-py, dz = pts[j*3+2]-pz;
        float d2 = fmaf(dx,dx, fmaf(dy,dy, dz*dz));
        sd[g][j] = d2;
        unsigned long long key = ((unsigned long long)__float_as_uint(d2) << 32) | (unsigned)j;
        lmin = minull(lmin, key);
    }

    for (int t=0; t<KKN; t++){
        unsigned long long tmp = lmin;
        #pragma unroll
        for (int o=16;o;o>>=1) tmp = minull(tmp, __shfl_xor_sync(0xffffffffu, tmp, o));
        if (lane == 0) wmin[g][wig] = tmp;
        __syncthreads();
        if (sub == 0){
            unsigned long long m = minull(minull(wmin[g][0], wmin[g][1]),
                                          minull(wmin[g][2], wmin[g][3]));
            best[g] = m;
            g_nb[i*KKN + t] = (int)(unsigned)m;
        }
        __syncthreads();
        unsigned long long b = best[g];
        int j = (int)(unsigned)b;
        if ((j & 127) == sub){
            unsigned long long nm = ~0ull;
            #pragma unroll 4
            for (int jj = sub; jj < PP; jj += KNN_TPR){
                unsigned long long key = ((unsigned long long)__float_as_uint(sd[g][jj]) << 32) | (unsigned)jj;
                if (key > b) nm = minull(nm, key);
            }
            lmin = nm;
        }
    }
}

// ---------------- K4: 3xTF32 tensor-core GEMM + row/col argmax ---------------
__device__ __forceinline__ void mma_tf32(float& d0, float& d1, float& d2, float& d3,
    unsigned a0, unsigned a1, unsigned a2, unsigned a3, unsigned b0, unsigned b1){
    asm volatile("mma.sync.aligned.m16n8k8.row.col.f32.tf32.tf32.f32 "
        "{%0,%1,%2,%3},{%4,%5,%6,%7},{%8,%9},{%0,%1,%2,%3};\n"
        : "+f"(d0),"+f"(d1),"+f"(d2),"+f"(d3)
        : "r"(a0),"r"(a1),"r"(a2),"r"(a3),"r"(b0),"r"(b1));
}

__global__ __launch_bounds__(256,2) void k_gemm(){
    __shared__ __align__(16) float As[128][36];
    __shared__ __align__(16) float Bs[128][36];
    int tid = threadIdx.x;
    int lane = tid & 31;
    int warp = tid >> 5;
    int wm = warp >> 2, wn = warp & 3;
    int g = lane >> 2, q = lane & 3;
    int r0 = blockIdx.y*128, c0 = blockIdx.x*128;
    int mb = wm*64, nb = wn*32;

    float acc[4][4][4];
    #pragma unroll
    for (int a=0;a<4;a++)
        #pragma unroll
        for (int b=0;b<4;b++)
            #pragma unroll
            for (int i2=0;i2<4;i2++) acc[a][b][i2] = 0.f;

    #pragma unroll 1
    for (int c=0;c<12;c++){
        const float* Ap = (c < 8) ? g_ahi : g_alo;             // hi,hi,lo
        const float* Bp = (c >= 4 && c < 8) ? g_blo : g_bhi;   // hi,lo,hi
        int k0 = (c & 3)*32;
        #pragma unroll
        for (int it=0; it<4; it++){
            int idx = it*256 + tid;
            int row = idx >> 3;
            int kk  = (idx & 7)*4;
            *(float4*)&As[row][kk] = *(const float4*)&Ap[(size_t)(r0+row)*CC + k0 + kk];
            *(float4*)&Bs[row][kk] = *(const float4*)&Bp[(size_t)(c0+row)*CC + k0 + kk];
        }
        __syncthreads();
        #pragma unroll
        for (int ks=0; ks<4; ks++){
            int kq = ks*8 + q;
            unsigned af[4][4], bf[4][2];
            #pragma unroll
            for (int t=0;t<4;t++){
                int m0 = mb + t*16 + g;
                af[t][0] = __float_as_uint(As[m0  ][kq  ]);
                af[t][1] = __float_as_uint(As[m0+8][kq  ]);
                af[t][2] = __float_as_uint(As[m0  ][kq+4]);
                af[t][3] = __float_as_uint(As[m0+8][kq+4]);
                int n0 = nb + t*8 + g;
                bf[t][0] = __float_as_uint(Bs[n0][kq  ]);
                bf[t][1] = __float_as_uint(Bs[n0][kq+4]);
            }
            #pragma unroll
            for (int tm=0; tm<4; tm++)
                #pragma unroll
                for (int tn=0; tn<4; tn++)
                    mma_tf32(acc[tm][tn][0], acc[tm][tn][1], acc[tm][tn][2], acc[tm][tn][3],
                             af[tm][0], af[tm][1], af[tm][2], af[tm][3],
                             bf[tn][0], bf[tn][1]);
        }
        __syncthreads();
    }

    // ---- epilogue: packed row/col argmax via shared u64 atomics ----
    unsigned long long* rowk = (unsigned long long*)&As[0][0];   // 128
    unsigned long long* colk = rowk + 128;                       // 128
    if (tid < 128){ rowk[tid] = 0ull; colk[tid] = 0ull; }
    __syncthreads();

    #pragma unroll
    for (int tm=0; tm<4; tm++){
        unsigned long long klo = 0ull, khi = 0ull;
        #pragma unroll
        for (int tn=0; tn<4; tn++){
            int n0 = c0 + nb + tn*8 + 2*q;
            klo = maxull(klo, KEYPACK(acc[tm][tn][0], n0));
            klo = maxull(klo, KEYPACK(acc[tm][tn][1], n0+1));
            khi = maxull(khi, KEYPACK(acc[tm][tn][2], n0));
            khi = maxull(khi, KEYPACK(acc[tm][tn][3], n0+1));
        }
        atomicMax(&rowk[mb + tm*16 + g    ], klo);
        atomicMax(&rowk[mb + tm*16 + g + 8], khi);
    }
    #pragma unroll
    for (int tn=0; tn<4; tn++){
        unsigned long long c0k = 0ull, c1k = 0ull;
        #pragma unroll
        for (int tm=0; tm<4; tm++){
            int m0 = r0 + mb + tm*16 + g;
            c0k = maxull(c0k, KEYPACK(acc[tm][tn][0], m0));
            c0k = maxull(c0k, KEYPACK(acc[tm][tn][2], m0+8));
            c1k = maxull(c1k, KEYPACK(acc[tm][tn][1], m0));
            c1k = maxull(c1k, KEYPACK(acc[tm][tn][3], m0+8));
        }
        atomicMax(&colk[nb + tn*8 + 2*q    ], c0k);
        atomicMax(&colk[nb + tn*8 + 2*q + 1], c1k);
    }
    __syncthreads();
    if (tid < 128) atomicMax(&g_rowbest[r0+tid], rowk[tid]);
    else           atomicMax(&g_colbest[c0+tid-128], colk[tid-128]);
}

// ---------------- K5: unpack packed argmax ----------------------------------
__global__ void k_unpack(){
    int i = blockIdx.x*blockDim.x + threadIdx.x;
    if (i >= PP) return;
    unsigned long long k1 = g_rowbest[i];
    g_imbs[i] = sort2f((unsigned)(k1 >> 32));
    g_imbi[i] = (int)(~(unsigned)k1);
    unsigned long long k2 = g_colbest[i];
    g_pcbs[i] = sort2f((unsigned)(k2 >> 32));
    g_pcbi[i] = (int)(~(unsigned)k2);
}

// ---------------- K6: im branch: batched sims, softmax, top-4, spot ---------
__global__ __launch_bounds__(128) void k_impix(float* __restrict__ sel_out){
    int warp = (blockIdx.x*blockDim.x + threadIdx.x) >> 5;
    int lane = threadIdx.x & 31;
    if (warp >= PP) return;
    int p = warp, h = p >> 7, w = p & 127;   // WW == 128
    float4 cf = ((const float4*)(g_nimf + (size_t)p*CC))[lane];

    // 25 independent gathers + per-lane partial dots (high MLP)
    float acc[KKN];
    #pragma unroll
    for (int k=0; k<KKN; k++){
        int di = k/5 - 2, dj = k%5 - 2;
        int hh = iclamp(h+di, 0, HH-1), ww = iclamp(w+dj, 0, WW-1);
        float4 nf = ((const float4*)(g_nimf + (size_t)(hh*WW+ww)*CC))[lane];
        acc[k] = fmaf(cf.x,nf.x, fmaf(cf.y,nf.y, fmaf(cf.z,nf.z, cf.w*nf.w)));
    }
    // 5 butterfly rounds of 25 INDEPENDENT shfls each (pipelined, not chained)
    #pragma unroll
    for (int o=16;o;o>>=1){
        #pragma unroll
        for (int k=0; k<KKN; k++) acc[k] += __shfl_xor_sync(0xffffffffu, acc[k], o);
    }
    // lane k takes value k (predicated selects; no dynamic indexing)
    float v = -FMAXV;
    #pragma unroll
    for (int k=0; k<KKN; k++) if (lane == k) v = acc[k];

    // softmax over lanes 0..24
    float m = v;
    #pragma unroll
    for (int o=16;o;o>>=1) m = fmaxf(m, __shfl_xor_sync(0xffffffffu, m, o));
    float e = (lane < KKN) ? expf(v - m) : 0.f;
    float su = e;
    #pragma unroll
    for (int o=16;o;o>>=1) su += __shfl_xor_sync(0xffffffffu, su, o);
    float soft = e / su;

    int di = lane/5 - 2, dj = lane%5 - 2;
    float selv = NEGV;
    if (lane < KKN){
        bool inb = ((unsigned)(h+di) < (unsigned)HH) && ((unsigned)(w+dj) < (unsigned)WW);
        int hh = iclamp(h+di, 0, HH-1), ww = iclamp(w+dj, 0, WW-1);
        float conf = g_imbs[hh*WW+ww];
        selv = inb ? soft*conf : NEGV;
        sel_out[(size_t)lane*PP + p] = selv;
    }
    float cand = (lane < KKN && lane != 12) ? selv : -FMAXV;
    #pragma unroll 1
    for (int s=0; s<SPOTN; s++){
        int kk;
        if (s == 0){
            kk = 12;
        } else {
            unsigned long long key = ((unsigned long long)f2sort(cand) << 32) | (unsigned)(31 - lane);
            #pragma unroll
            for (int o=16;o;o>>=1){
                unsigned long long ok = __shfl_xor_sync(0xffffffffu, key, o);
                if (ok > key) key = ok;
            }
            kk = 31 - (int)(key & 0xffffffffull);
            if (lane == kk) cand = -FMAXV;
        }
        int q = (h + kk/5 - 2)*WW + (w + kk%5 - 2);
        int sd = g_imbi[q];
        if (lane < KKN) g_spot_im[(size_t)p*125 + s*25 + lane] = g_nb[sd*KKN + lane];
    }
}

// ---------------- K7: pc branch (batched) ------------------------------------
__global__ __launch_bounds__(128) void k_pcpoint(){
    int warp = (blockIdx.x*blockDim.x + threadIdx.x) >> 5;
    int lane = threadIdx.x & 31;
    if (warp >= PP) return;
    int p = warp;
    float4 cf = ((const float4*)(g_npcf + (size_t)p*CC))[lane];

    int nbk[KKN];
    #pragma unroll
    for (int k=0; k<KKN; k++) nbk[k] = g_nb[p*KKN + k];

    float acc[KKN];
    #pragma unroll
    for (int k=0; k<KKN; k++){
        float4 nf = ((const float4*)(g_npcf + (size_t)nbk[k]*CC))[lane];
        acc[k] = fmaf(cf.x,nf.x, fmaf(cf.y,nf.y, fmaf(cf.z,nf.z, cf.w*nf.w)));
    }
    #pragma unroll
    for (int o=16;o;o>>=1){
        #pragma unroll
        for (int k=0; k<KKN; k++) acc[k] += __shfl_xor_sync(0xffffffffu, acc[k], o);
    }
    float v = -FMAXV; int myq = 0;
    #pragma unroll
    for (int k=0; k<KKN; k++) if (lane == k){ v = acc[k]; myq = nbk[k]; }

    float m = v;
    #pragma unroll
    for (int o=16;o;o>>=1) m = fmaxf(m, __shfl_xor_sync(0xffffffffu, m, o));
    float e = (lane < KKN) ? expf(v - m) : 0.f;
    float su = e;
    #pragma unroll
    for (int o=16;o;o>>=1) su += __shfl_xor_sync(0xffffffffu, su, o);
    float soft = e / su;

    float selv = NEGV;
    if (lane < KKN) selv = (lane == 0) ? NEGV : soft * g_pcbs[myq];
    float cand = (lane >= 1 && lane < KKN) ? selv : -FMAXV;
    #pragma unroll 1
    for (int s=0; s<SPOTN; s++){
        int kk;
        if (s == 0){
            kk = 0;
        } else {
            unsigned long long key = ((unsigned long long)f2sort(cand) << 32) | (unsigned)(31 - lane);
            #pragma unroll
            for (int o=16;o;o>>=1){
                unsigned long long ok = __shfl_xor_sync(0xffffffffu, key, o);
                if (ok > key) key = ok;
            }
            kk = 31 - (int)(key & 0xffffffffull);
            if (lane == kk) cand = -FMAXV;
        }
        int qq = __shfl_sync(0xffffffffu, myq, kk);
        int pix = g_pcbi[qq];
        int pr = pix >> 7, pc = pix & 127;
        if (lane < KKN){
            int rr = iclamp(pr + lane/5 - 2, 0, HH-1);
            int cc = iclamp(pc + lane%5 - 2, 0, WW-1);
            g_spot_pc[(size_t)p*125 + s*25 + lane] = rr*WW + cc;
        }
    }
}

// ---------------- K8: scatter mask + stable top-125 (bitmask scan) ----------
__global__ __launch_bounds__(256) void k_mask(int which,
                                              float* __restrict__ omask,
                                              float* __restrict__ oidx){
    __shared__ unsigned bm[32][160];
    const int* spot = which ? g_spot_pc : g_spot_im;
    int r0 = blockIdx.x*32;
    int tid = threadIdx.x;
    for (int i=tid; i<32*160; i+=256) ((unsigned*)bm)[i] = 0u;
    __syncthreads();
    for (int e=tid; e<32*125; e+=256){
        int row = e / 125;
        int v = spot[(size_t)(r0+row)*125 + (e % 125)];
        atomicOr(&bm[row][v>>5], 1u << (v & 31));
    }
    __syncthreads();
    if (tid < 32){
        int row = tid, t = 0;
        float* om = omask + (size_t)(r0+row)*125;
        float* oi = oidx  + (size_t)(r0+row)*125;
        for (int w2=0; w2<160; w2++){
            unsigned x = bm[row][w2];
            while (x){
                int b = __ffs(x) - 1; x &= x - 1;
                oi[t] = (float)(w2*32 + b); om[t] = 1.f; t++;
            }
        }
        for (int j=0; t<125; j++){
            if (!((bm[row][j>>5] >> (j&31)) & 1u)){
                oi[t] = (float)j; om[t] = 0.f; t++;
            }
        }
    }
}

// ---------------- launch ------------------------------------------------------
extern "C" void kernel_launch(void* const* d_in, const int* in_sizes, int n_in,
                              void* d_out, int out_size){
    const float* imf = (const float*)d_in[0];
    const float* pcf = (const float*)d_in[1];
    const float* pts = (const float*)d_in[2];
    float* out = (float*)d_out;

    float* sel_out     = out;                       // 25*5120
    float* mask_out    = out + 25*PP;               // 5120*125
    float* idx_out     = out + 25*PP + 125*PP;      // 5120*125
    float* idx_pc_out  = out + 25*PP + 2*125*PP;    // 5120*125
    float* mask_pc_out = out + 25*PP + 3*125*PP;    // 5120*125

    // NOTE: launch order chosen so ncu's captured launch (4th) is k_gemm.
    k_norm<<<(PP*32 + 255)/256, 256>>>(imf, 0);   // 1
    k_norm<<<(PP*32 + 255)/256, 256>>>(pcf, 1);   // 2
    k_knn<<<PP/KNN_ROWS, 256>>>(pts);             // 3
    k_gemm<<<dim3(PP/128, PP/128), 256>>>();      // 4  <- profiled
    k_unpack<<<(PP+255)/256, 256>>>();            // 5
    k_impix<<<PP/4, 128>>>(sel_out);              // 6
    k_pcpoint<<<PP/4, 128>>>();                   // 7
    k_mask<<<PP/32, 256>>>(0, mask_out, idx_out); // 8
    k_mask<<<PP/32, 256>>>(1, mask_pc_out, idx_pc_out); // 9
}

// round 9
// speedup vs baseline: 1.0673x; 1.0217x over previous
#include <cuda_runtime.h>

#define HH 40
#define WW 128
#define PP 5120
#define CC 128
#define KKN 25
#define SPOTN 5
#define NEGV (-1e8f)
#define FMAXV 3.402823466e38f

// ---------------- scratch (device globals; no allocations allowed) ----------
__device__ float g_nimf[PP*CC];
__device__ float g_npcf[PP*CC];
__device__ float g_ahi[PP*CC];   // tf32 hi/lo splits of normalized imf
__device__ float g_alo[PP*CC];
__device__ float g_bhi[PP*CC];   // tf32 hi/lo splits of normalized pcf
__device__ float g_blo[PP*CC];
__device__ int   g_nb[PP*KKN];
__device__ unsigned long long g_rowbest[PP];
__device__ unsigned long long g_colbest[PP];
__device__ float g_imbs[PP];   // best_score per pixel
__device__ int   g_imbi[PP];   // best_index per pixel (pc idx)
__device__ float g_pcbs[PP];   // best_pc_score per point
__device__ int   g_pcbi[PP];   // best_pc_idx per point (pixel idx)
__device__ int   g_spot_im[PP*125];
__device__ int   g_spot_pc[PP*125];

__device__ __forceinline__ unsigned f2sort(float f){
    unsigned b = __float_as_uint(f);
    return (b & 0x80000000u) ? ~b : (b | 0x80000000u);
}
__device__ __forceinline__ float sort2f(unsigned u){
    unsigned b = (u & 0x80000000u) ? (u & 0x7fffffffu) : ~u;
    return __uint_as_float(b);
}
__device__ __forceinline__ int iclamp(int v, int lo, int hi){
    return v < lo ? lo : (v > hi ? hi : v);
}
__device__ __forceinline__ unsigned long long maxull(unsigned long long a, unsigned long long b){
    return a > b ? a : b;
}
__device__ __forceinline__ unsigned long long minull(unsigned long long a, unsigned long long b){
    return a < b ? a : b;
}
__device__ __forceinline__ float tf32r(float x){
    unsigned u; asm("cvt.rna.tf32.f32 %0, %1;" : "=r"(u) : "f"(x));
    return __uint_as_float(u);
}
__device__ __forceinline__ void cpasync16(unsigned s, const float* g){
    asm volatile("cp.async.cg.shared.global [%0], [%1], 16;\n" :: "r"(s), "l"(g));
}
#define KEYPACK(v,n) ((((unsigned long long)f2sort(v)) << 32) | (unsigned)(~(n)))

// ---------------- K1a/K1b: L2 normalize + tf32 hi/lo split ------------------
__global__ __launch_bounds__(256) void k_norm(const float* __restrict__ src,
                                              int which){
    int gt = blockIdx.x*blockDim.x + threadIdx.x;
    if (!which && gt < PP){ g_rowbest[gt] = 0ull; g_colbest[gt] = 0ull; }
    int r = gt >> 5;
    int lane = threadIdx.x & 31;
    if (r >= PP) return;
    float* dst = which ? g_npcf : g_nimf;
    float* dhi = which ? g_bhi : g_ahi;
    float* dlo = which ? g_blo : g_alo;
    float4 v = ((const float4*)(src + (size_t)r*CC))[lane];
    float ss = v.x*v.x + v.y*v.y + v.z*v.z + v.w*v.w;
    #pragma unroll
    for (int o=16;o;o>>=1) ss += __shfl_xor_sync(0xffffffffu, ss, o);
    float inv = 1.0f / fmaxf(sqrtf(ss), 1e-12f);
    v.x*=inv; v.y*=inv; v.z*=inv; v.w*=inv;
    ((float4*)(dst + (size_t)r*CC))[lane] = v;
    float4 hi, lo;
    hi.x = tf32r(v.x); lo.x = tf32r(v.x - hi.x);
    hi.y = tf32r(v.y); lo.y = tf32r(v.y - hi.y);
    hi.z = tf32r(v.z); lo.z = tf32r(v.z - hi.z);
    hi.w = tf32r(v.w); lo.w = tf32r(v.w - hi.w);
    ((float4*)(dhi + (size_t)r*CC))[lane] = hi;
    ((float4*)(dlo + (size_t)r*CC))[lane] = lo;
}

// ---------------- K3: knn (top-25 nearest, self first, tie->lower idx) ------
#define KNN_ROWS 2
#define KNN_TPR  128
__global__ __launch_bounds__(256) void k_knn(const float* __restrict__ pts){
    __shared__ float sd[KNN_ROWS][PP];                 // 40 KB
    __shared__ unsigned long long wmin[KNN_ROWS][4];
    __shared__ unsigned long long best[KNN_ROWS];
    int tid  = threadIdx.x;
    int g    = tid >> 7;
    int sub  = tid & 127;
    int lane = tid & 31;
    int wig  = (tid >> 5) & 3;
    int i = blockIdx.x*KNN_ROWS + g;
    float px = pts[i*3+0], py = pts[i*3+1], pz = pts[i*3+2];

    unsigned long long lmin = ~0ull;
    for (int j = sub; j < PP; j += KNN_TPR){
        float dx = pts[j*3+0]-px, dy = pts[j*3+1]-py, dz = pts[j*3+2]-pz;
        float d2 = fmaf(dx,dx, fmaf(dy,dy, dz*dz));
        sd[g][j] = d2;
        unsigned long long key = ((unsigned long long)__float_as_uint(d2) << 32) | (unsigned)j;
        lmin = minull(lmin, key);
    }

    for (int t=0; t<KKN; t++){
        unsigned long long tmp = lmin;
        #pragma unroll
        for (int o=16;o;o>>=1) tmp = minull(tmp, __shfl_xor_sync(0xffffffffu, tmp, o));
        if (lane == 0) wmin[g][wig] = tmp;
        __syncthreads();
        if (sub == 0){
            unsigned long long m = minull(minull(wmin[g][0], wmin[g][1]),
                                          minull(wmin[g][2], wmin[g][3]));
            best[g] = m;
            g_nb[i*KKN + t] = (int)(unsigned)m;
        }
        __syncthreads();
        unsigned long long b = best[g];
        int j = (int)(unsigned)b;
        if ((j & 127) == sub){
            unsigned long long nm = ~0ull;
            #pragma unroll 4
            for (int jj = sub; jj < PP; jj += KNN_TPR){
                unsigned long long key = ((unsigned long long)__float_as_uint(sd[g][jj]) << 32) | (unsigned)jj;
                if (key > b) nm = minull(nm, key);
            }
            lmin = nm;
        }
    }
}

// ---------------- K4: 3xTF32 tensor-core GEMM, cp.async 2-stage pipeline ----
// S = nimf @ npcf^T as Ahi·Bhi + Ahi·Blo + Alo·Bhi (12 virtual 32-K chunks).
// Dynamic smem: 2 stages x (As 128x36 + Bs 128x36) floats = 73728 B.
__device__ __forceinline__ void mma_tf32(float& d0, float& d1, float& d2, float& d3,
    unsigned a0, unsigned a1, unsigned a2, unsigned a3, unsigned b0, unsigned b1){
    asm volatile("mma.sync.aligned.m16n8k8.row.col.f32.tf32.tf32.f32 "
        "{%0,%1,%2,%3},{%4,%5,%6,%7},{%8,%9},{%0,%1,%2,%3};\n"
        : "+f"(d0),"+f"(d1),"+f"(d2),"+f"(d3)
        : "r"(a0),"r"(a1),"r"(a2),"r"(a3),"r"(b0),"r"(b1));
}

#define GSTAGE 9216          // floats per stage (2 * 128*36)
#define GHALF  4608          // floats per matrix (128*36)

__device__ __forceinline__ void gemm_issue(unsigned sbase, int st, int c,
                                           int r0, int c0, int tid){
    const float* Ap = (c < 8) ? g_ahi : g_alo;             // hi,hi,lo
    const float* Bp = (c >= 4 && c < 8) ? g_blo : g_bhi;   // hi,lo,hi
    int k0 = (c & 3)*32;
    unsigned abase = sbase + (unsigned)st*(GSTAGE*4);
    unsigned bbase = abase + GHALF*4;
    #pragma unroll
    for (int it=0; it<4; it++){
        int idx = it*256 + tid;
        int row = idx >> 3;
        int kk  = (idx & 7)*4;
        cpasync16(abase + row*144 + kk*4, Ap + (size_t)(r0+row)*CC + k0 + kk);
        cpasync16(bbase + row*144 + kk*4, Bp + (size_t)(c0+row)*CC + k0 + kk);
    }
    asm volatile("cp.async.commit_group;\n");
}

__global__ __launch_bounds__(256,2) void k_gemm(){
    extern __shared__ __align__(16) float dynsmem[];
    unsigned sbase = (unsigned)__cvta_generic_to_shared(dynsmem);
    int tid = threadIdx.x;
    int lane = tid & 31;
    int warp = tid >> 5;
    int wm = warp >> 2, wn = warp & 3;
    int g = lane >> 2, q = lane & 3;
    int r0 = blockIdx.y*128, c0 = blockIdx.x*128;
    int mb = wm*64, nb = wn*32;

    float acc[4][4][4];
    #pragma unroll
    for (int a=0;a<4;a++)
        #pragma unroll
        for (int b=0;b<4;b++)
            #pragma unroll
            for (int i2=0;i2<4;i2++) acc[a][b][i2] = 0.f;

    gemm_issue(sbase, 0, 0, r0, c0, tid);
    gemm_issue(sbase, 1, 1, r0, c0, tid);

    #pragma unroll 1
    for (int c=0;c<12;c++){
        if (c < 11) asm volatile("cp.async.wait_group 1;\n");
        else        asm volatile("cp.async.wait_group 0;\n");
        __syncthreads();
        const float* As = dynsmem + (c & 1)*GSTAGE;
        const float* Bs = As + GHALF;
        #pragma unroll
        for (int ks=0; ks<4; ks++){
            int kq = ks*8 + q;
            unsigned af[4][4], bf[4][2];
            #pragma unroll
            for (int t=0;t<4;t++){
                int m0 = mb + t*16 + g;
                af[t][0] = __float_as_uint(As[(m0  )*36 + kq  ]);
                af[t][1] = __float_as_uint(As[(m0+8)*36 + kq  ]);
                af[t][2] = __float_as_uint(As[(m0  )*36 + kq+4]);
                af[t][3] = __float_as_uint(As[(m0+8)*36 + kq+4]);
                int n0 = nb + t*8 + g;
                bf[t][0] = __float_as_uint(Bs[n0*36 + kq  ]);
                bf[t][1] = __float_as_uint(Bs[n0*36 + kq+4]);
            }
            #pragma unroll
            for (int tm=0; tm<4; tm++)
                #pragma unroll
                for (int tn=0; tn<4; tn++)
                    mma_tf32(acc[tm][tn][0], acc[tm][tn][1], acc[tm][tn][2], acc[tm][tn][3],
                             af[tm][0], af[tm][1], af[tm][2], af[tm][3],
                             bf[tn][0], bf[tn][1]);
        }
        __syncthreads();
        if (c < 10) gemm_issue(sbase, c & 1, c + 2, r0, c0, tid);
    }

    // ---- epilogue: packed row/col argmax via shared u64 atomics ----
    unsigned long long* rowk = (unsigned long long*)dynsmem;     // 128
    unsigned long long* colk = rowk + 128;                       // 128
    if (tid < 128){ rowk[tid] = 0ull; colk[tid] = 0ull; }
    __syncthreads();

    #pragma unroll
    for (int tm=0; tm<4; tm++){
        unsigned long long klo = 0ull, khi = 0ull;
        #pragma unroll
        for (int tn=0; tn<4; tn++){
            int n0 = c0 + nb + tn*8 + 2*q;
            klo = maxull(klo, KEYPACK(acc[tm][tn][0], n0));
            klo = maxull(klo, KEYPACK(acc[tm][tn][1], n0+1));
            khi = maxull(khi, KEYPACK(acc[tm][tn][2], n0));
            khi = maxull(khi, KEYPACK(acc[tm][tn][3], n0+1));
        }
        atomicMax(&rowk[mb + tm*16 + g    ], klo);
        atomicMax(&rowk[mb + tm*16 + g + 8], khi);
    }
    #pragma unroll
    for (int tn=0; tn<4; tn++){
        unsigned long long c0k = 0ull, c1k = 0ull;
        #pragma unroll
        for (int tm=0; tm<4; tm++){
            int m0 = r0 + mb + tm*16 + g;
            c0k = maxull(c0k, KEYPACK(acc[tm][tn][0], m0));
            c0k = maxull(c0k, KEYPACK(acc[tm][tn][2], m0+8));
            c1k = maxull(c1k, KEYPACK(acc[tm][tn][1], m0));
            c1k = maxull(c1k, KEYPACK(acc[tm][tn][3], m0+8));
        }
        atomicMax(&colk[nb + tn*8 + 2*q    ], c0k);
        atomicMax(&colk[nb + tn*8 + 2*q + 1], c1k);
    }
    __syncthreads();
    if (tid < 128) atomicMax(&g_rowbest[r0+tid], rowk[tid]);
    else           atomicMax(&g_colbest[c0+tid-128], colk[tid-128]);
}

// ---------------- K5: unpack packed argmax ----------------------------------
__global__ void k_unpack(){
    int i = blockIdx.x*blockDim.x + threadIdx.x;
    if (i >= PP) return;
    unsigned long long k1 = g_rowbest[i];
    g_imbs[i] = sort2f((unsigned)(k1 >> 32));
    g_imbi[i] = (int)(~(unsigned)k1);
    unsigned long long k2 = g_colbest[i];
    g_pcbs[i] = sort2f((unsigned)(k2 >> 32));
    g_pcbi[i] = (int)(~(unsigned)k2);
}

// ---------------- K6: im branch: batched sims, softmax, top-4, spot ---------
__global__ __launch_bounds__(128) void k_impix(float* __restrict__ sel_out){
    int warp = (blockIdx.x*blockDim.x + threadIdx.x) >> 5;
    int lane = threadIdx.x & 31;
    if (warp >= PP) return;
    int p = warp, h = p >> 7, w = p & 127;   // WW == 128
    float4 cf = ((const float4*)(g_nimf + (size_t)p*CC))[lane];

    float acc[KKN];
    #pragma unroll
    for (int k=0; k<KKN; k++){
        int di = k/5 - 2, dj = k%5 - 2;
        int hh = iclamp(h+di, 0, HH-1), ww = iclamp(w+dj, 0, WW-1);
        float4 nf = ((const float4*)(g_nimf + (size_t)(hh*WW+ww)*CC))[lane];
        acc[k] = fmaf(cf.x,nf.x, fmaf(cf.y,nf.y, fmaf(cf.z,nf.z, cf.w*nf.w)));
    }
    #pragma unroll
    for (int o=16;o;o>>=1){
        #pragma unroll
        for (int k=0; k<KKN; k++) acc[k] += __shfl_xor_sync(0xffffffffu, acc[k], o);
    }
    float v = -FMAXV;
    #pragma unroll
    for (int k=0; k<KKN; k++) if (lane == k) v = acc[k];

    float m = v;
    #pragma unroll
    for (int o=16;o;o>>=1) m = fmaxf(m, __shfl_xor_sync(0xffffffffu, m, o));
    float e = (lane < KKN) ? expf(v - m) : 0.f;
    float su = e;
    #pragma unroll
    for (int o=16;o;o>>=1) su += __shfl_xor_sync(0xffffffffu, su, o);
    float soft = e / su;

    int di = lane/5 - 2, dj = lane%5 - 2;
    float selv = NEGV;
    if (lane < KKN){
        bool inb = ((unsigned)(h+di) < (unsigned)HH) && ((unsigned)(w+dj) < (unsigned)WW);
        int hh = iclamp(h+di, 0, HH-1), ww = iclamp(w+dj, 0, WW-1);
        float conf = g_imbs[hh*WW+ww];
        selv = inb ? soft*conf : NEGV;
        sel_out[(size_t)lane*PP + p] = selv;
    }
    float cand = (lane < KKN && lane != 12) ? selv : -FMAXV;
    #pragma unroll 1
    for (int s=0; s<SPOTN; s++){
        int kk;
        if (s == 0){
            kk = 12;
        } else {
            unsigned long long key = ((unsigned long long)f2sort(cand) << 32) | (unsigned)(31 - lane);
            #pragma unroll
            for (int o=16;o;o>>=1){
                unsigned long long ok = __shfl_xor_sync(0xffffffffu, key, o);
                if (ok > key) key = ok;
            }
            kk = 31 - (int)(key & 0xffffffffull);
            if (lane == kk) cand = -FMAXV;
        }
        int q = (h + kk/5 - 2)*WW + (w + kk%5 - 2);
        int sd = g_imbi[q];
        if (lane < KKN) g_spot_im[(size_t)p*125 + s*25 + lane] = g_nb[sd*KKN + lane];
    }
}

// ---------------- K7: pc branch (batched) ------------------------------------
__global__ __launch_bounds__(128) void k_pcpoint(){
    int warp = (blockIdx.x*blockDim.x + threadIdx.x) >> 5;
    int lane = threadIdx.x & 31;
    if (warp >= PP) return;
    int p = warp;
    float4 cf = ((const float4*)(g_npcf + (size_t)p*CC))[lane];

    int nbk[KKN];
    #pragma unroll
    for (int k=0; k<KKN; k++) nbk[k] = g_nb[p*KKN + k];

    float acc[KKN];
    #pragma unroll
    for (int k=0; k<KKN; k++){
        float4 nf = ((const float4*)(g_npcf + (size_t)nbk[k]*CC))[lane];
        acc[k] = fmaf(cf.x,nf.x, fmaf(cf.y,nf.y, fmaf(cf.z,nf.z, cf.w*nf.w)));
    }
    #pragma unroll
    for (int o=16;o;o>>=1){
        #pragma unroll
        for (int k=0; k<KKN; k++) acc[k] += __shfl_xor_sync(0xffffffffu, acc[k], o);
    }
    float v = -FMAXV; int myq = 0;
    #pragma unroll
    for (int k=0; k<KKN; k++) if (lane == k){ v = acc[k]; myq = nbk[k]; }

    float m = v;
    #pragma unroll
    for (int o=16;o;o>>=1) m = fmaxf(m, __shfl_xor_sync(0xffffffffu, m, o));
    float e = (lane < KKN) ? expf(v - m) : 0.f;
    float su = e;
    #pragma unroll
    for (int o=16;o;o>>=1) su += __shfl_xor_sync(0xffffffffu, su, o);
    float soft = e / su;

    float selv = NEGV;
    if (lane < KKN) selv = (lane == 0) ? NEGV : soft * g_pcbs[myq];
    float cand = (lane >= 1 && lane < KKN) ? selv : -FMAXV;
    #pragma unroll 1
    for (int s=0; s<SPOTN; s++){
        int kk;
        if (s == 0){
            kk = 0;
        } else {
            unsigned long long key = ((unsigned long long)f2sort(cand) << 32) | (unsigned)(31 - lane);
            #pragma unroll
            for (int o=16;o;o>>=1){
                unsigned long long ok = __shfl_xor_sync(0xffffffffu, key, o);
                if (ok > key) key = ok;
            }
            kk = 31 - (int)(key & 0xffffffffull);
            if (lane == kk) cand = -FMAXV;
        }
        int qq = __shfl_sync(0xffffffffu, myq, kk);
        int pix = g_pcbi[qq];
        int pr = pix >> 7, pc = pix & 127;
        if (lane < KKN){
            int rr = iclamp(pr + lane/5 - 2, 0, HH-1);
            int cc = iclamp(pc + lane%5 - 2, 0, WW-1);
            g_spot_pc[(size_t)p*125 + s*25 + lane] = rr*WW + cc;
        }
    }
}

// ---------------- K8: scatter mask + stable top-125 (bitmask scan) ----------
__global__ __launch_bounds__(256) void k_mask(int which,
                                              float* __restrict__ omask,
                                              float* __restrict__ oidx){
    __shared__ unsigned bm[32][160];
    const int* spot = which ? g_spot_pc : g_spot_im;
    int r0 = blockIdx.x*32;
    int tid = threadIdx.x;
    for (int i=tid; i<32*160; i+=256) ((unsigned*)bm)[i] = 0u;
    __syncthreads();
    for (int e=tid; e<32*125; e+=256){
        int row = e / 125;
        int v = spot[(size_t)(r0+row)*125 + (e % 125)];
        atomicOr(&bm[row][v>>5], 1u << (v & 31));
    }
    __syncthreads();
    if (tid < 32){
        int row = tid, t = 0;
        float* om = omask + (size_t)(r0+row)*125;
        float* oi = oidx  + (size_t)(r0+row)*125;
        for (int w2=0; w2<160; w2++){
            unsigned x = bm[row][w2];
            while (x){
                int b = __ffs(x) - 1; x &= x - 1;
                oi[t] = (float)(w2*32 + b); om[t] = 1.f; t++;
            }
        }
        for (int j=0; t<125; j++){
            if (!((bm[row][j>>5] >> (j&31)) & 1u)){
                oi[t] = (float)j; om[t] = 0.f; t++;
            }
        }
    }
}

// ---------------- launch ------------------------------------------------------
extern "C" void kernel_launch(void* const* d_in, const int* in_sizes, int n_in,
                              void* d_out, int out_size){
    const float* imf = (const float*)d_in[0];
    const float* pcf = (const float*)d_in[1];
    const float* pts = (const float*)d_in[2];
    float* out = (float*)d_out;

    float* sel_out     = out;                       // 25*5120
    float* mask_out    = out + 25*PP;               // 5120*125
    float* idx_out     = out + 25*PP + 125*PP;      // 5120*125
    float* idx_pc_out  = out + 25*PP + 2*125*PP;    // 5120*125
    float* mask_pc_out = out + 25*PP + 3*125*PP;    // 5120*125

    cudaFuncSetAttribute(k_gemm, cudaFuncAttributeMaxDynamicSharedMemorySize, 73728);

    // NOTE: launch order chosen so ncu's captured launch (4th) is k_knn.
    k_norm<<<(PP*32 + 255)/256, 256>>>(imf, 0);            // 1
    k_norm<<<(PP*32 + 255)/256, 256>>>(pcf, 1);            // 2
    k_gemm<<<dim3(PP/128, PP/128), 256, 73728>>>();        // 3
    k_knn<<<PP/KNN_ROWS, 256>>>(pts);                      // 4  <- profiled
    k_unpack<<<(PP+255)/256, 256>>>();                     // 5
    k_impix<<<PP/4, 128>>>(sel_out);                       // 6
    k_pcpoint<<<PP/4, 128>>>();                            // 7
    k_mask<<<PP/32, 256>>>(0, mask_out, idx_out);          // 8
    k_mask<<<PP/32, 256>>>(1, mask_pc_out, idx_pc_out);    // 9
}

// round 10
// speedup vs baseline: 1.3198x; 1.2366x over previous
#include <cuda_runtime.h>

#define HH 40
#define WW 128
#define PP 5120
#define CC 128
#define KKN 25
#define SPOTN 5
#define NEGV (-1e8f)
#define FMAXV 3.402823466e38f
#define SENTK 0xffffffffffffffffull

// ---------------- scratch (device globals; no allocations allowed) ----------
__device__ float g_nimf[PP*CC];
__device__ float g_npcf[PP*CC];
__device__ float g_ahi[PP*CC];   // tf32 hi/lo splits of normalized imf
__device__ float g_alo[PP*CC];
__device__ float g_bhi[PP*CC];   // tf32 hi/lo splits of normalized pcf
__device__ float g_blo[PP*CC];
__device__ int   g_nb[PP*KKN];
__device__ unsigned long long g_rowbest[PP];
__device__ unsigned long long g_colbest[PP];
__device__ float g_imbs[PP];   // best_score per pixel
__device__ int   g_imbi[PP];   // best_index per pixel (pc idx)
__device__ float g_pcbs[PP];   // best_pc_score per point
__device__ int   g_pcbi[PP];   // best_pc_idx per point (pixel idx)
__device__ int   g_spot_im[PP*125];
__device__ int   g_spot_pc[PP*125];

__device__ __forceinline__ unsigned f2sort(float f){
    unsigned b = __float_as_uint(f);
    return (b & 0x80000000u) ? ~b : (b | 0x80000000u);
}
__device__ __forceinline__ float sort2f(unsigned u){
    unsigned b = (u & 0x80000000u) ? (u & 0x7fffffffu) : ~u;
    return __uint_as_float(b);
}
__device__ __forceinline__ int iclamp(int v, int lo, int hi){
    return v < lo ? lo : (v > hi ? hi : v);
}
__device__ __forceinline__ unsigned long long maxull(unsigned long long a, unsigned long long b){
    return a > b ? a : b;
}
__device__ __forceinline__ unsigned long long minull(unsigned long long a, unsigned long long b){
    return a < b ? a : b;
}
__device__ __forceinline__ float tf32r(float x){
    unsigned u; asm("cvt.rna.tf32.f32 %0, %1;" : "=r"(u) : "f"(x));
    return __uint_as_float(u);
}
__device__ __forceinline__ void cpasync16(unsigned s, const float* g){
    asm volatile("cp.async.cg.shared.global [%0], [%1], 16;\n" :: "r"(s), "l"(g));
}
#define KEYPACK(v,n) ((((unsigned long long)f2sort(v)) << 32) | (unsigned)(~(n)))

// ---------------- K1a/K1b: L2 normalize + tf32 hi/lo split ------------------
__global__ __launch_bounds__(256) void k_norm(const float* __restrict__ src,
                                              int which){
    int gt = blockIdx.x*blockDim.x + threadIdx.x;
    if (!which && gt < PP){ g_rowbest[gt] = 0ull; g_colbest[gt] = 0ull; }
    int r = gt >> 5;
    int lane = threadIdx.x & 31;
    if (r >= PP) return;
    float* dst = which ? g_npcf : g_nimf;
    float* dhi = which ? g_bhi : g_ahi;
    float* dlo = which ? g_blo : g_alo;
    float4 v = ((const float4*)(src + (size_t)r*CC))[lane];
    float ss = v.x*v.x + v.y*v.y + v.z*v.z + v.w*v.w;
    #pragma unroll
    for (int o=16;o;o>>=1) ss += __shfl_xor_sync(0xffffffffu, ss, o);
    float inv = 1.0f / fmaxf(sqrtf(ss), 1e-12f);
    v.x*=inv; v.y*=inv; v.z*=inv; v.w*=inv;
    ((float4*)(dst + (size_t)r*CC))[lane] = v;
    float4 hi, lo;
    hi.x = tf32r(v.x); lo.x = tf32r(v.x - hi.x);
    hi.y = tf32r(v.y); lo.y = tf32r(v.y - hi.y);
    hi.z = tf32r(v.z); lo.z = tf32r(v.z - hi.z);
    hi.w = tf32r(v.w); lo.w = tf32r(v.w - hi.w);
    ((float4*)(dhi + (size_t)r*CC))[lane] = hi;
    ((float4*)(dlo + (size_t)r*CC))[lane] = lo;
}

// ---------------- K3: knn, warp-per-row, per-lane top-4 caches ---------------
// Keys (d2_bits<<32 | j): min order == (d2 asc, idx asc) == top_k(-d2) order.
// Lane l owns stripe j = l+32t (160 elems), keeps its 4 smallest keys sorted in
// registers. Extraction = warp-min of lane heads; owner pops; if a lane's cache
// empties (rare), it refills by rescanning its stripe for keys > last extracted
// (valid because extraction order is globally ascending).
#define KNN_WARPS 8
__global__ __launch_bounds__(KNN_WARPS*32) void k_knn(const float* __restrict__ pts){
    int warp = threadIdx.x >> 5;
    int lane = threadIdx.x & 31;
    int i = blockIdx.x*KNN_WARPS + warp;
    float px = pts[3*i+0], py = pts[3*i+1], pz = pts[3*i+2];

    unsigned long long k0=SENTK,k1=SENTK,k2=SENTK,k3=SENTK;
    for (int j=lane; j<PP; j+=32){
        float dx = pts[3*j+0]-px, dy = pts[3*j+1]-py, dz = pts[3*j+2]-pz;
        float d2 = fmaf(dx,dx, fmaf(dy,dy, dz*dz));   // same expr as before
        unsigned long long key = ((unsigned long long)__float_as_uint(d2) << 32) | (unsigned)j;
        if (key < k3){
            k3 = key;
            if (k3 < k2){ unsigned long long t=k2; k2=k3; k3=t; }
            if (k2 < k1){ unsigned long long t=k1; k1=k2; k2=t; }
            if (k1 < k0){ unsigned long long t=k0; k0=k1; k1=t; }
        }
    }

    #pragma unroll 1
    for (int t=0; t<KKN; t++){
        unsigned long long m = k0;
        #pragma unroll
        for (int o=16;o;o>>=1) m = minull(m, __shfl_xor_sync(0xffffffffu, m, o));
        unsigned own = __ballot_sync(0xffffffffu, k0 == m);
        if (lane == 0) g_nb[i*KKN + t] = (int)(unsigned)m;
        if (own & (1u << lane)){
            k0 = k1; k1 = k2; k2 = k3; k3 = SENTK;
            if (k0 == SENTK){
                // refill cache with 4 smallest stripe keys > m (recompute d2)
                #pragma unroll 1
                for (int j=lane; j<PP; j+=32){
                    float dx = pts[3*j+0]-px, dy = pts[3*j+1]-py, dz = pts[3*j+2]-pz;
                    float d2 = fmaf(dx,dx, fmaf(dy,dy, dz*dz));
                    unsigned long long key = ((unsigned long long)__float_as_uint(d2) << 32) | (unsigned)j;
                    if (key > m && key < k3){
                        k3 = key;
                        if (k3 < k2){ unsigned long long q=k2; k2=k3; k3=q; }
                        if (k2 < k1){ unsigned long long q=k1; k1=k2; k2=q; }
                        if (k1 < k0){ unsigned long long q=k0; k0=k1; k1=q; }
                    }
                }
            }
        }
    }
}

// ---------------- K4: 3xTF32 tensor-core GEMM, cp.async 2-stage pipeline ----
__device__ __forceinline__ void mma_tf32(float& d0, float& d1, float& d2, float& d3,
    unsigned a0, unsigned a1, unsigned a2, unsigned a3, unsigned b0, unsigned b1){
    asm volatile("mma.sync.aligned.m16n8k8.row.col.f32.tf32.tf32.f32 "
        "{%0,%1,%2,%3},{%4,%5,%6,%7},{%8,%9},{%0,%1,%2,%3};\n"
        : "+f"(d0),"+f"(d1),"+f"(d2),"+f"(d3)
        : "r"(a0),"r"(a1),"r"(a2),"r"(a3),"r"(b0),"r"(b1));
}

#define GSTAGE 9216          // floats per stage (2 * 128*36)
#define GHALF  4608          // floats per matrix (128*36)

__device__ __forceinline__ void gemm_issue(unsigned sbase, int st, int c,
                                           int r0, int c0, int tid){
    const float* Ap = (c < 8) ? g_ahi : g_alo;             // hi,hi,lo
    const float* Bp = (c >= 4 && c < 8) ? g_blo : g_bhi;   // hi,lo,hi
    int k0 = (c & 3)*32;
    unsigned abase = sbase + (unsigned)st*(GSTAGE*4);
    unsigned bbase = abase + GHALF*4;
    #pragma unroll
    for (int it=0; it<4; it++){
        int idx = it*256 + tid;
        int row = idx >> 3;
        int kk  = (idx & 7)*4;
        cpasync16(abase + row*144 + kk*4, Ap + (size_t)(r0+row)*CC + k0 + kk);
        cpasync16(bbase + row*144 + kk*4, Bp + (size_t)(c0+row)*CC + k0 + kk);
    }
    asm volatile("cp.async.commit_group;\n");
}

__global__ __launch_bounds__(256,2) void k_gemm(){
    extern __shared__ __align__(16) float dynsmem[];
    unsigned sbase = (unsigned)__cvta_generic_to_shared(dynsmem);
    int tid = threadIdx.x;
    int lane = tid & 31;
    int warp = tid >> 5;
    int wm = warp >> 2, wn = warp & 3;
    int g = lane >> 2, q = lane & 3;
    int r0 = blockIdx.y*128, c0 = blockIdx.x*128;
    int mb = wm*64, nb = wn*32;

    float acc[4][4][4];
    #pragma unroll
    for (int a=0;a<4;a++)
        #pragma unroll
        for (int b=0;b<4;b++)
            #pragma unroll
            for (int i2=0;i2<4;i2++) acc[a][b][i2] = 0.f;

    gemm_issue(sbase, 0, 0, r0, c0, tid);
    gemm_issue(sbase, 1, 1, r0, c0, tid);

    #pragma unroll 1
    for (int c=0;c<12;c++){
        if (c < 11) asm volatile("cp.async.wait_group 1;\n");
        else        asm volatile("cp.async.wait_group 0;\n");
        __syncthreads();
        const float* As = dynsmem + (c & 1)*GSTAGE;
        const float* Bs = As + GHALF;
        #pragma unroll
        for (int ks=0; ks<4; ks++){
            int kq = ks*8 + q;
            unsigned af[4][4], bf[4][2];
            #pragma unroll
            for (int t=0;t<4;t++){
                int m0 = mb + t*16 + g;
                af[t][0] = __float_as_uint(As[(m0  )*36 + kq  ]);
                af[t][1] = __float_as_uint(As[(m0+8)*36 + kq  ]);
                af[t][2] = __float_as_uint(As[(m0  )*36 + kq+4]);
                af[t][3] = __float_as_uint(As[(m0+8)*36 + kq+4]);
                int n0 = nb + t*8 + g;
                bf[t][0] = __float_as_uint(Bs[n0*36 + kq  ]);
                bf[t][1] = __float_as_uint(Bs[n0*36 + kq+4]);
            }
            #pragma unroll
            for (int tm=0; tm<4; tm++)
                #pragma unroll
                for (int tn=0; tn<4; tn++)
                    mma_tf32(acc[tm][tn][0], acc[tm][tn][1], acc[tm][tn][2], acc[tm][tn][3],
                             af[tm][0], af[tm][1], af[tm][2], af[tm][3],
                             bf[tn][0], bf[tn][1]);
        }
        __syncthreads();
        if (c < 10) gemm_issue(sbase, c & 1, c + 2, r0, c0, tid);
    }

    // ---- epilogue: packed row/col argmax via shared u64 atomics ----
    unsigned long long* rowk = (unsigned long long*)dynsmem;     // 128
    unsigned long long* colk = rowk + 128;                       // 128
    if (tid < 128){ rowk[tid] = 0ull; colk[tid] = 0ull; }
    __syncthreads();

    #pragma unroll
    for (int tm=0; tm<4; tm++){
        unsigned long long klo = 0ull, khi = 0ull;
        #pragma unroll
        for (int tn=0; tn<4; tn++){
            int n0 = c0 + nb + tn*8 + 2*q;
            klo = maxull(klo, KEYPACK(acc[tm][tn][0], n0));
            klo = maxull(klo, KEYPACK(acc[tm][tn][1], n0+1));
            khi = maxull(khi, KEYPACK(acc[tm][tn][2], n0));
            khi = maxull(khi, KEYPACK(acc[tm][tn][3], n0+1));
        }
        atomicMax(&rowk[mb + tm*16 + g    ], klo);
        atomicMax(&rowk[mb + tm*16 + g + 8], khi);
    }
    #pragma unroll
    for (int tn=0; tn<4; tn++){
        unsigned long long c0k = 0ull, c1k = 0ull;
        #pragma unroll
        for (int tm=0; tm<4; tm++){
            int m0 = r0 + mb + tm*16 + g;
            c0k = maxull(c0k, KEYPACK(acc[tm][tn][0], m0));
            c0k = maxull(c0k, KEYPACK(acc[tm][tn][2], m0+8));
            c1k = maxull(c1k, KEYPACK(acc[tm][tn][1], m0));
            c1k = maxull(c1k, KEYPACK(acc[tm][tn][3], m0+8));
        }
        atomicMax(&colk[nb + tn*8 + 2*q    ], c0k);
        atomicMax(&colk[nb + tn*8 + 2*q + 1], c1k);
    }
    __syncthreads();
    if (tid < 128) atomicMax(&g_rowbest[r0+tid], rowk[tid]);
    else           atomicMax(&g_colbest[c0+tid-128], colk[tid-128]);
}

// ---------------- K5: unpack packed argmax ----------------------------------
__global__ void k_unpack(){
    int i = blockIdx.x*blockDim.x + threadIdx.x;
    if (i >= PP) return;
    unsigned long long k1 = g_rowbest[i];
    g_imbs[i] = sort2f((unsigned)(k1 >> 32));
    g_imbi[i] = (int)(~(unsigned)k1);
    unsigned long long k2 = g_colbest[i];
    g_pcbs[i] = sort2f((unsigned)(k2 >> 32));
    g_pcbi[i] = (int)(~(unsigned)k2);
}

// ---------------- K6: im branch: batched sims, softmax, top-4, spot ---------
__global__ __launch_bounds__(128) void k_impix(float* __restrict__ sel_out){
    int warp = (blockIdx.x*blockDim.x + threadIdx.x) >> 5;
    int lane = threadIdx.x & 31;
    if (warp >= PP) return;
    int p = warp, h = p >> 7, w = p & 127;   // WW == 128
    float4 cf = ((const float4*)(g_nimf + (size_t)p*CC))[lane];

    float acc[KKN];
    #pragma unroll
    for (int k=0; k<KKN; k++){
        int di = k/5 - 2, dj = k%5 - 2;
        int hh = iclamp(h+di, 0, HH-1), ww = iclamp(w+dj, 0, WW-1);
        float4 nf = ((const float4*)(g_nimf + (size_t)(hh*WW+ww)*CC))[lane];
        acc[k] = fmaf(cf.x,nf.x, fmaf(cf.y,nf.y, fmaf(cf.z,nf.z, cf.w*nf.w)));
    }
    #pragma unroll
    for (int o=16;o;o>>=1){
        #pragma unroll
        for (int k=0; k<KKN; k++) acc[k] += __shfl_xor_sync(0xffffffffu, acc[k], o);
    }
    float v = -FMAXV;
    #pragma unroll
    for (int k=0; k<KKN; k++) if (lane == k) v = acc[k];

    float m = v;
    #pragma unroll
    for (int o=16;o;o>>=1) m = fmaxf(m, __shfl_xor_sync(0xffffffffu, m, o));
    float e = (lane < KKN) ? expf(v - m) : 0.f;
    float su = e;
    #pragma unroll
    for (int o=16;o;o>>=1) su += __shfl_xor_sync(0xffffffffu, su, o);
    float soft = e / su;

    int di = lane/5 - 2, dj = lane%5 - 2;
    float selv = NEGV;
    if (lane < KKN){
        bool inb = ((unsigned)(h+di) < (unsigned)HH) && ((unsigned)(w+dj) < (unsigned)WW);
        int hh = iclamp(h+di, 0, HH-1), ww = iclamp(w+dj, 0, WW-1);
        float conf = g_imbs[hh*WW+ww];
        selv = inb ? soft*conf : NEGV;
        sel_out[(size_t)lane*PP + p] = selv;
    }
    float cand = (lane < KKN && lane != 12) ? selv : -FMAXV;
    #pragma unroll 1
    for (int s=0; s<SPOTN; s++){
        int kk;
        if (s == 0){
            kk = 12;
        } else {
            unsigned long long key = ((unsigned long long)f2sort(cand) << 32) | (unsigned)(31 - lane);
            #pragma unroll
            for (int o=16;o;o>>=1){
                unsigned long long ok = __shfl_xor_sync(0xffffffffu, key, o);
                if (ok > key) key = ok;
            }
            kk = 31 - (int)(key & 0xffffffffull);
            if (lane == kk) cand = -FMAXV;
        }
        int q = (h + kk/5 - 2)*WW + (w + kk%5 - 2);
        int sd = g_imbi[q];
        if (lane < KKN) g_spot_im[(size_t)p*125 + s*25 + lane] = g_nb[sd*KKN + lane];
    }
}

// ---------------- K7: pc branch (batched) ------------------------------------
__global__ __launch_bounds__(128) void k_pcpoint(){
    int warp = (blockIdx.x*blockDim.x + threadIdx.x) >> 5;
    int lane = threadIdx.x & 31;
    if (warp >= PP) return;
    int p = warp;
    float4 cf = ((const float4*)(g_npcf + (size_t)p*CC))[lane];

    int nbk[KKN];
    #pragma unroll
    for (int k=0; k<KKN; k++) nbk[k] = g_nb[p*KKN + k];

    float acc[KKN];
    #pragma unroll
    for (int k=0; k<KKN; k++){
        float4 nf = ((const float4*)(g_npcf + (size_t)nbk[k]*CC))[lane];
        acc[k] = fmaf(cf.x,nf.x, fmaf(cf.y,nf.y, fmaf(cf.z,nf.z, cf.w*nf.w)));
    }
    #pragma unroll
    for (int o=16;o;o>>=1){
        #pragma unroll
        for (int k=0; k<KKN; k++) acc[k] += __shfl_xor_sync(0xffffffffu, acc[k], o);
    }
    float v = -FMAXV; int myq = 0;
    #pragma unroll
    for (int k=0; k<KKN; k++) if (lane == k){ v = acc[k]; myq = nbk[k]; }

    float m = v;
    #pragma unroll
    for (int o=16;o;o>>=1) m = fmaxf(m, __shfl_xor_sync(0xffffffffu, m, o));
    float e = (lane < KKN) ? expf(v - m) : 0.f;
    float su = e;
    #pragma unroll
    for (int o=16;o;o>>=1) su += __shfl_xor_sync(0xffffffffu, su, o);
    float soft = e / su;

    float selv = NEGV;
    if (lane < KKN) selv = (lane == 0) ? NEGV : soft * g_pcbs[myq];
    float cand = (lane >= 1 && lane < KKN) ? selv : -FMAXV;
    #pragma unroll 1
    for (int s=0; s<SPOTN; s++){
        int kk;
        if (s == 0){
            kk = 0;
        } else {
            unsigned long long key = ((unsigned long long)f2sort(cand) << 32) | (unsigned)(31 - lane);
            #pragma unroll
            for (int o=16;o;o>>=1){
                unsigned long long ok = __shfl_xor_sync(0xffffffffu, key, o);
                if (ok > key) key = ok;
            }
            kk = 31 - (int)(key & 0xffffffffull);
            if (lane == kk) cand = -FMAXV;
        }
        int qq = __shfl_sync(0xffffffffu, myq, kk);
        int pix = g_pcbi[qq];
        int pr = pix >> 7, pc = pix & 127;
        if (lane < KKN){
            int rr = iclamp(pr + lane/5 - 2, 0, HH-1);
            int cc = iclamp(pc + lane%5 - 2, 0, WW-1);
            g_spot_pc[(size_t)p*125 + s*25 + lane] = rr*WW + cc;
        }
    }
}

// ---------------- K8: scatter mask + stable top-125 (bitmask scan) ----------
__global__ __launch_bounds__(256) void k_mask(int which,
                                              float* __restrict__ omask,
                                              float* __restrict__ oidx){
    __shared__ unsigned bm[32][160];
    const int* spot = which ? g_spot_pc : g_spot_im;
    int r0 = blockIdx.x*32;
    int tid = threadIdx.x;
    for (int i=tid; i<32*160; i+=256) ((unsigned*)bm)[i] = 0u;
    __syncthreads();
    for (int e=tid; e<32*125; e+=256){
        int row = e / 125;
        int v = spot[(size_t)(r0+row)*125 + (e % 125)];
        atomicOr(&bm[row][v>>5], 1u << (v & 31));
    }
    __syncthreads();
    if (tid < 32){
        int row = tid, t = 0;
        float* om = omask + (size_t)(r0+row)*125;
        float* oi = oidx  + (size_t)(r0+row)*125;
        for (int w2=0; w2<160; w2++){
            unsigned x = bm[row][w2];
            while (x){
                int b = __ffs(x) - 1; x &= x - 1;
                oi[t] = (float)(w2*32 + b); om[t] = 1.f; t++;
            }
        }
        for (int j=0; t<125; j++){
            if (!((bm[row][j>>5] >> (j&31)) & 1u)){
                oi[t] = (float)j; om[t] = 0.f; t++;
            }
        }
    }
}

// ---------------- launch ------------------------------------------------------
extern "C" void kernel_launch(void* const* d_in, const int* in_sizes, int n_in,
                              void* d_out, int out_size){
    const float* imf = (const float*)d_in[0];
    const float* pcf = (const float*)d_in[1];
    const float* pts = (const float*)d_in[2];
    float* out = (float*)d_out;

    float* sel_out     = out;                       // 25*5120
    float* mask_out    = out + 25*PP;               // 5120*125
    float* idx_out     = out + 25*PP + 125*PP;      // 5120*125
    float* idx_pc_out  = out + 25*PP + 2*125*PP;    // 5120*125
    float* mask_pc_out = out + 25*PP + 3*125*PP;    // 5120*125

    cudaFuncSetAttribute(k_gemm, cudaFuncAttributeMaxDynamicSharedMemorySize, 73728);

    // NOTE: launch order chosen so ncu's captured launch (4th) is k_gemm.
    k_norm<<<(PP*32 + 255)/256, 256>>>(imf, 0);            // 1
    k_norm<<<(PP*32 + 255)/256, 256>>>(pcf, 1);            // 2
    k_knn<<<PP/KNN_WARPS, KNN_WARPS*32>>>(pts);            // 3
    k_gemm<<<dim3(PP/128, PP/128), 256, 73728>>>();        // 4  <- profiled
    k_unpack<<<(PP+255)/256, 256>>>();                     // 5
    k_impix<<<PP/4, 128>>>(sel_out);                       // 6
    k_pcpoint<<<PP/4, 128>>>();                            // 7
    k_mask<<<PP/32, 256>>>(0, mask_out, idx_out);          // 8
    k_mask<<<PP/32, 256>>>(1, mask_pc_out, idx_pc_out);    // 9
}

// round 11
// speedup vs baseline: 1.3977x; 1.0590x over previous
#include <cuda_runtime.h>

#define HH 40
#define WW 128
#define PP 5120
#define CC 128
#define KKN 25
#define SPOTN 5
#define NEGV (-1e8f)
#define FMAXV 3.402823466e38f
#define SENTK 0xffffffffffffffffull

// ---------------- scratch (device globals; no allocations allowed) ----------
__device__ float g_nimf[PP*CC];
__device__ float g_npcf[PP*CC];
__device__ float g_ahi[PP*CC];   // A fragments (imf) hi, mma-fragment layout
__device__ float g_alo[PP*CC];   // A fragments lo
__device__ float g_bhi[PP*CC];   // B fragments (pcf) hi
__device__ float g_blo[PP*CC];   // B fragments lo
__device__ int   g_nb[PP*KKN];
__device__ unsigned long long g_rowbest[PP];
__device__ unsigned long long g_colbest[PP];
__device__ float g_imbs[PP];   // best_score per pixel
__device__ int   g_imbi[PP];   // best_index per pixel (pc idx)
__device__ float g_pcbs[PP];   // best_pc_score per point
__device__ int   g_pcbi[PP];   // best_pc_idx per point (pixel idx)
__device__ int   g_spot_im[PP*125];
__device__ int   g_spot_pc[PP*125];

__device__ __forceinline__ unsigned f2sort(float f){
    unsigned b = __float_as_uint(f);
    return (b & 0x80000000u) ? ~b : (b | 0x80000000u);
}
__device__ __forceinline__ float sort2f(unsigned u){
    unsigned b = (u & 0x80000000u) ? (u & 0x7fffffffu) : ~u;
    return __uint_as_float(b);
}
__device__ __forceinline__ int iclamp(int v, int lo, int hi){
    return v < lo ? lo : (v > hi ? hi : v);
}
__device__ __forceinline__ unsigned long long maxull(unsigned long long a, unsigned long long b){
    return a > b ? a : b;
}
__device__ __forceinline__ unsigned long long minull(unsigned long long a, unsigned long long b){
    return a < b ? a : b;
}
__device__ __forceinline__ float tf32r(float x){
    unsigned u; asm("cvt.rna.tf32.f32 %0, %1;" : "=r"(u) : "f"(x));
    return __uint_as_float(u);
}
__device__ __forceinline__ void cpasync16(unsigned s, const float* g){
    asm volatile("cp.async.cg.shared.global [%0], [%1], 16;\n" :: "r"(s), "l"(g));
}
#define KEYPACK(v,n) ((((unsigned long long)f2sort(v)) << 32) | (unsigned)(~(n)))

// ---------------- K1a/K1b: L2 normalize -------------------------------------
__global__ __launch_bounds__(256) void k_norm(const float* __restrict__ src,
                                              int which){
    int gt = blockIdx.x*blockDim.x + threadIdx.x;
    if (!which && gt < PP){ g_rowbest[gt] = 0ull; g_colbest[gt] = 0ull; }
    int r = gt >> 5;
    int lane = threadIdx.x & 31;
    if (r >= PP) return;
    float* dst = which ? g_npcf : g_nimf;
    float4 v = ((const float4*)(src + (size_t)r*CC))[lane];
    float ss = v.x*v.x + v.y*v.y + v.z*v.z + v.w*v.w;
    #pragma unroll
    for (int o=16;o;o>>=1) ss += __shfl_xor_sync(0xffffffffu, ss, o);
    float inv = 1.0f / fmaxf(sqrtf(ss), 1e-12f);
    v.x*=inv; v.y*=inv; v.z*=inv; v.w*=inv;
    ((float4*)(dst + (size_t)r*CC))[lane] = v;
}

// ---------------- K2: tf32 hi/lo split into mma-fragment layout --------------
// A-frag (imf): per 16x8 tile (mt,kt), lane(g=l>>2,q=l&3) holds float4
//   (A[g][q], A[g+8][q], A[g][q+4], A[g+4+... q+4]) at float4 idx (mt*16+kt)*32+lane.
// B-frag (pcf): per 8x8 tile (nt,kt), lane holds float2 (B[g][q], B[g][q+4])
//   at float2 idx (nt*16+kt)*32+lane.
__global__ __launch_bounds__(256) void k_pack(){
    int b = blockIdx.x;
    int tid = threadIdx.x;
    if (b < PP/16){
        int mt = b;
        #pragma unroll
        for (int s = tid; s < 512; s += 256){
            int kt = s >> 5, lane = s & 31;
            int g = lane >> 2, q = lane & 3;
            const float* base = g_nimf + (size_t)(mt*16)*CC + kt*8;
            float x0 = base[g*CC + q];
            float x1 = base[(g+8)*CC + q];
            float x2 = base[g*CC + q + 4];
            float x3 = base[(g+8)*CC + q + 4];
            float4 hi, lo;
            hi.x = tf32r(x0); lo.x = tf32r(x0 - hi.x);
            hi.y = tf32r(x1); lo.y = tf32r(x1 - hi.y);
            hi.z = tf32r(x2); lo.z = tf32r(x2 - hi.z);
            hi.w = tf32r(x3); lo.w = tf32r(x3 - hi.w);
            int o = (mt*16 + kt)*32 + lane;
            ((float4*)g_ahi)[o] = hi;
            ((float4*)g_alo)[o] = lo;
        }
    } else {
        int nt = b - PP/16;
        #pragma unroll
        for (int s = tid; s < 512; s += 256){
            int kt = s >> 5, lane = s & 31;
            int g = lane >> 2, q = lane & 3;
            const float* base = g_npcf + (size_t)(nt*8 + g)*CC + kt*8;
            float x0 = base[q], x1 = base[q+4];
            float2 hi, lo;
            hi.x = tf32r(x0); lo.x = tf32r(x0 - hi.x);
            hi.y = tf32r(x1); lo.y = tf32r(x1 - hi.y);
            int o = (nt*16 + kt)*32 + lane;
            ((float2*)g_bhi)[o] = hi;
            ((float2*)g_blo)[o] = lo;
        }
    }
}

// ---------------- K3: knn, warp-per-row, per-lane top-4 caches ---------------
#define KNN_WARPS 8
__global__ __launch_bounds__(KNN_WARPS*32) void k_knn(const float* __restrict__ pts){
    int warp = threadIdx.x >> 5;
    int lane = threadIdx.x & 31;
    int i = blockIdx.x*KNN_WARPS + warp;
    float px = pts[3*i+0], py = pts[3*i+1], pz = pts[3*i+2];

    unsigned long long k0=SENTK,k1=SENTK,k2=SENTK,k3=SENTK;
    for (int j=lane; j<PP; j+=32){
        float dx = pts[3*j+0]-px, dy = pts[3*j+1]-py, dz = pts[3*j+2]-pz;
        float d2 = fmaf(dx,dx, fmaf(dy,dy, dz*dz));
        unsigned long long key = ((unsigned long long)__float_as_uint(d2) << 32) | (unsigned)j;
        if (key < k3){
            k3 = key;
            if (k3 < k2){ unsigned long long t=k2; k2=k3; k3=t; }
            if (k2 < k1){ unsigned long long t=k1; k1=k2; k2=t; }
            if (k1 < k0){ unsigned long long t=k0; k0=k1; k1=t; }
        }
    }

    #pragma unroll 1
    for (int t=0; t<KKN; t++){
        unsigned long long m = k0;
        #pragma unroll
        for (int o=16;o;o>>=1) m = minull(m, __shfl_xor_sync(0xffffffffu, m, o));
        unsigned own = __ballot_sync(0xffffffffu, k0 == m);
        if (lane == 0) g_nb[i*KKN + t] = (int)(unsigned)m;
        if (own & (1u << lane)){
            k0 = k1; k1 = k2; k2 = k3; k3 = SENTK;
            if (k0 == SENTK){
                #pragma unroll 1
                for (int j=lane; j<PP; j+=32){
                    float dx = pts[3*j+0]-px, dy = pts[3*j+1]-py, dz = pts[3*j+2]-pz;
                    float d2 = fmaf(dx,dx, fmaf(dy,dy, dz*dz));
                    unsigned long long key = ((unsigned long long)__float_as_uint(d2) << 32) | (unsigned)j;
                    if (key > m && key < k3){
                        k3 = key;
                        if (k3 < k2){ unsigned long long q=k2; k2=k3; k3=q; }
                        if (k2 < k1){ unsigned long long q=k1; k1=k2; k2=q; }
                        if (k1 < k0){ unsigned long long q=k0; k0=k1; k1=q; }
                    }
                }
            }
        }
    }
}

// ---------------- K4: 3xTF32 GEMM, fragment-packed smem, 3-stage cp.async ---
__device__ __forceinline__ void mma_tf32(float& d0, float& d1, float& d2, float& d3,
    unsigned a0, unsigned a1, unsigned a2, unsigned a3, unsigned b0, unsigned b1){
    asm volatile("mma.sync.aligned.m16n8k8.row.col.f32.tf32.tf32.f32 "
        "{%0,%1,%2,%3},{%4,%5,%6,%7},{%8,%9},{%0,%1,%2,%3};\n"
        : "+f"(d0),"+f"(d1),"+f"(d2),"+f"(d3)
        : "r"(a0),"r"(a1),"r"(a2),"r"(a3),"r"(b0),"r"(b1));
}

#define STAGE_BYTES 32768u   // A 16KB (1024 float4) + B 16KB (2048 float2)
#define STAGE_FLOATS 8192

// stage st <- chunk c. A: 8 m-tiles x 4 kt x 32 lanes float4 (linear copy).
//                      B: 16 n-tiles x 4 kt x 32 lanes float2 (linear copy).
__device__ __forceinline__ void gemm_issue(unsigned sbase, int st, int c,
                                           int r0, int c0, int tid){
    const float* Ap = (c < 8) ? g_ahi : g_alo;             // hi,hi,lo
    const float* Bp = (c >= 4 && c < 8) ? g_blo : g_bhi;   // hi,lo,hi
    int kt0 = (c & 3)*4;
    int mt0 = r0 >> 4;
    int nt0 = c0 >> 3;
    unsigned abase = sbase + (unsigned)st*STAGE_BYTES;
    unsigned bbase = abase + 16384u;
    #pragma unroll
    for (int it=0; it<4; it++){
        int idx = it*256 + tid;
        int ga = (mt0 + (idx>>7))*512 + kt0*32 + (idx & 127);      // float4 units
        cpasync16(abase + idx*16, Ap + (size_t)ga*4);
        int gb = (nt0 + (idx>>6))*512 + kt0*32 + ((idx & 63)*2);   // float2 units
        cpasync16(bbase + idx*16, Bp + (size_t)gb*2);
    }
    asm volatile("cp.async.commit_group;\n");
}

__global__ __launch_bounds__(256,2) void k_gemm(){
    extern __shared__ __align__(16) float dynsmem[];
    unsigned sbase = (unsigned)__cvta_generic_to_shared(dynsmem);
    int tid = threadIdx.x;
    int lane = tid & 31;
    int warp = tid >> 5;
    int wm = warp >> 2, wn = warp & 3;
    int g = lane >> 2, q = lane & 3;
    int r0 = blockIdx.y*128, c0 = blockIdx.x*128;
    int mb = wm*64, nb = wn*32;

    float acc[4][4][4];
    #pragma unroll
    for (int a=0;a<4;a++)
        #pragma unroll
        for (int b=0;b<4;b++)
            #pragma unroll
            for (int i2=0;i2<4;i2++) acc[a][b][i2] = 0.f;

    gemm_issue(sbase, 0, 0, r0, c0, tid);
    gemm_issue(sbase, 1, 1, r0, c0, tid);
    gemm_issue(sbase, 2, 2, r0, c0, tid);

    #pragma unroll 1
    for (int c=0;c<12;c++){
        if (c <= 9)       asm volatile("cp.async.wait_group 2;\n");
        else if (c == 10) asm volatile("cp.async.wait_group 1;\n");
        else              asm volatile("cp.async.wait_group 0;\n");
        __syncthreads();
        const float4* sA = (const float4*)(dynsmem + (c % 3)*STAGE_FLOATS);
        const float2* sB = (const float2*)(dynsmem + (c % 3)*STAGE_FLOATS + 4096);
        #pragma unroll
        for (int ks=0; ks<4; ks++){
            float4 a4[4]; float2 b2[4];
            #pragma unroll
            for (int t=0;t<4;t++){
                a4[t] = sA[((wm*4 + t)*4 + ks)*32 + lane];
                b2[t] = sB[((wn*4 + t)*4 + ks)*32 + lane];
            }
            #pragma unroll
            for (int tm=0; tm<4; tm++)
                #pragma unroll
                for (int tn=0; tn<4; tn++)
                    mma_tf32(acc[tm][tn][0], acc[tm][tn][1], acc[tm][tn][2], acc[tm][tn][3],
                             __float_as_uint(a4[tm].x), __float_as_uint(a4[tm].y),
                             __float_as_uint(a4[tm].z), __float_as_uint(a4[tm].w),
                             __float_as_uint(b2[tn].x), __float_as_uint(b2[tn].y));
        }
        __syncthreads();
        if (c <= 8) gemm_issue(sbase, c % 3, c + 3, r0, c0, tid);
    }

    // ---- epilogue: packed row/col argmax via shared u64 atomics ----
    unsigned long long* rowk = (unsigned long long*)dynsmem;     // 128
    unsigned long long* colk = rowk + 128;                       // 128
    if (tid < 128){ rowk[tid] = 0ull; colk[tid] = 0ull; }
    __syncthreads();

    #pragma unroll
    for (int tm=0; tm<4; tm++){
        unsigned long long klo = 0ull, khi = 0ull;
        #pragma unroll
        for (int tn=0; tn<4; tn++){
            int n0 = c0 + nb + tn*8 + 2*q;
            klo = maxull(klo, KEYPACK(acc[tm][tn][0], n0));
            klo = maxull(klo, KEYPACK(acc[tm][tn][1], n0+1));
            khi = maxull(khi, KEYPACK(acc[tm][tn][2], n0));
            khi = maxull(khi, KEYPACK(acc[tm][tn][3], n0+1));
        }
        atomicMax(&rowk[mb + tm*16 + g    ], klo);
        atomicMax(&rowk[mb + tm*16 + g + 8], khi);
    }
    #pragma unroll
    for (int tn=0; tn<4; tn++){
        unsigned long long c0k = 0ull, c1k = 0ull;
        #pragma unroll
        for (int tm=0; tm<4; tm++){
            int m0 = r0 + mb + tm*16 + g;
            c0k = maxull(c0k, KEYPACK(acc[tm][tn][0], m0));
            c0k = maxull(c0k, KEYPACK(acc[tm][tn][2], m0+8));
            c1k = maxull(c1k, KEYPACK(acc[tm][tn][1], m0));
            c1k = maxull(c1k, KEYPACK(acc[tm][tn][3], m0+8));
        }
        atomicMax(&colk[nb + tn*8 + 2*q    ], c0k);
        atomicMax(&colk[nb + tn*8 + 2*q + 1], c1k);
    }
    __syncthreads();
    if (tid < 128) atomicMax(&g_rowbest[r0+tid], rowk[tid]);
    else           atomicMax(&g_colbest[c0+tid-128], colk[tid-128]);
}

// ---------------- K5: unpack packed argmax ----------------------------------
__global__ void k_unpack(){
    int i = blockIdx.x*blockDim.x + threadIdx.x;
    if (i >= PP) return;
    unsigned long long k1 = g_rowbest[i];
    g_imbs[i] = sort2f((unsigned)(k1 >> 32));
    g_imbi[i] = (int)(~(unsigned)k1);
    unsigned long long k2 = g_colbest[i];
    g_pcbs[i] = sort2f((unsigned)(k2 >> 32));
    g_pcbi[i] = (int)(~(unsigned)k2);
}

// ---------------- K6: im branch: batched sims, softmax, top-4, spot ---------
__global__ __launch_bounds__(128) void k_impix(float* __restrict__ sel_out){
    int warp = (blockIdx.x*blockDim.x + threadIdx.x) >> 5;
    int lane = threadIdx.x & 31;
    if (warp >= PP) return;
    int p = warp, h = p >> 7, w = p & 127;   // WW == 128
    float4 cf = ((const float4*)(g_nimf + (size_t)p*CC))[lane];

    float acc[KKN];
    #pragma unroll
    for (int k=0; k<KKN; k++){
        int di = k/5 - 2, dj = k%5 - 2;
        int hh = iclamp(h+di, 0, HH-1), ww = iclamp(w+dj, 0, WW-1);
        float4 nf = ((const float4*)(g_nimf + (size_t)(hh*WW+ww)*CC))[lane];
        acc[k] = fmaf(cf.x,nf.x, fmaf(cf.y,nf.y, fmaf(cf.z,nf.z, cf.w*nf.w)));
    }
    #pragma unroll
    for (int o=16;o;o>>=1){
        #pragma unroll
        for (int k=0; k<KKN; k++) acc[k] += __shfl_xor_sync(0xffffffffu, acc[k], o);
    }
    float v = -FMAXV;
    #pragma unroll
    for (int k=0; k<KKN; k++) if (lane == k) v = acc[k];

    float m = v;
    #pragma unroll
    for (int o=16;o;o>>=1) m = fmaxf(m, __shfl_xor_sync(0xffffffffu, m, o));
    float e = (lane < KKN) ? expf(v - m) : 0.f;
    float su = e;
    #pragma unroll
    for (int o=16;o;o>>=1) su += __shfl_xor_sync(0xffffffffu, su, o);
    float soft = e / su;

    int di = lane/5 - 2, dj = lane%5 - 2;
    float selv = NEGV;
    if (lane < KKN){
        bool inb = ((unsigned)(h+di) < (unsigned)HH) && ((unsigned)(w+dj) < (unsigned)WW);
        int hh = iclamp(h+di, 0, HH-1), ww = iclamp(w+dj, 0, WW-1);
        float conf = g_imbs[hh*WW+ww];
        selv = inb ? soft*conf : NEGV;
        sel_out[(size_t)lane*PP + p] = selv;
    }
    float cand = (lane < KKN && lane != 12) ? selv : -FMAXV;
    #pragma unroll 1
    for (int s=0; s<SPOTN; s++){
        int kk;
        if (s == 0){
            kk = 12;
        } else {
            unsigned long long key = ((unsigned long long)f2sort(cand) << 32) | (unsigned)(31 - lane);
            #pragma unroll
            for (int o=16;o;o>>=1){
                unsigned long long ok = __shfl_xor_sync(0xffffffffu, key, o);
                if (ok > key) key = ok;
            }
            kk = 31 - (int)(key & 0xffffffffull);
            if (lane == kk) cand = -FMAXV;
        }
        int q = (h + kk/5 - 2)*WW + (w + kk%5 - 2);
        int sd = g_imbi[q];
        if (lane < KKN) g_spot_im[(size_t)p*125 + s*25 + lane] = g_nb[sd*KKN + lane];
    }
}

// ---------------- K7: pc branch (batched) ------------------------------------
__global__ __launch_bounds__(128) void k_pcpoint(){
    int warp = (blockIdx.x*blockDim.x + threadIdx.x) >> 5;
    int lane = threadIdx.x & 31;
    if (warp >= PP) return;
    int p = warp;
    float4 cf = ((const float4*)(g_npcf + (size_t)p*CC))[lane];

    int nbk[KKN];
    #pragma unroll
    for (int k=0; k<KKN; k++) nbk[k] = g_nb[p*KKN + k];

    float acc[KKN];
    #pragma unroll
    for (int k=0; k<KKN; k++){
        float4 nf = ((const float4*)(g_npcf + (size_t)nbk[k]*CC))[lane];
        acc[k] = fmaf(cf.x,nf.x, fmaf(cf.y,nf.y, fmaf(cf.z,nf.z, cf.w*nf.w)));
    }
    #pragma unroll
    for (int o=16;o;o>>=1){
        #pragma unroll
        for (int k=0; k<KKN; k++) acc[k] += __shfl_xor_sync(0xffffffffu, acc[k], o);
    }
    float v = -FMAXV; int myq = 0;
    #pragma unroll
    for (int k=0; k<KKN; k++) if (lane == k){ v = acc[k]; myq = nbk[k]; }

    float m = v;
    #pragma unroll
    for (int o=16;o;o>>=1) m = fmaxf(m, __shfl_xor_sync(0xffffffffu, m, o));
    float e = (lane < KKN) ? expf(v - m) : 0.f;
    float su = e;
    #pragma unroll
    for (int o=16;o;o>>=1) su += __shfl_xor_sync(0xffffffffu, su, o);
    float soft = e / su;

    float selv = NEGV;
    if (lane < KKN) selv = (lane == 0) ? NEGV : soft * g_pcbs[myq];
    float cand = (lane >= 1 && lane < KKN) ? selv : -FMAXV;
    #pragma unroll 1
    for (int s=0; s<SPOTN; s++){
        int kk;
        if (s == 0){
            kk = 0;
        } else {
            unsigned long long key = ((unsigned long long)f2sort(cand) << 32) | (unsigned)(31 - lane);
            #pragma unroll
            for (int o=16;o;o>>=1){
                unsigned long long ok = __shfl_xor_sync(0xffffffffu, key, o);
                if (ok > key) key = ok;
            }
            kk = 31 - (int)(key & 0xffffffffull);
            if (lane == kk) cand = -FMAXV;
        }
        int qq = __shfl_sync(0xffffffffu, myq, kk);
        int pix = g_pcbi[qq];
        int pr = pix >> 7, pc = pix & 127;
        if (lane < KKN){
            int rr = iclamp(pr + lane/5 - 2, 0, HH-1);
            int cc = iclamp(pc + lane%5 - 2, 0, WW-1);
            g_spot_pc[(size_t)p*125 + s*25 + lane] = rr*WW + cc;
        }
    }
}

// ---------------- K8: scatter mask + stable top-125 (bitmask scan) ----------
__global__ __launch_bounds__(256) void k_mask(int which,
                                              float* __restrict__ omask,
                                              float* __restrict__ oidx){
    __shared__ unsigned bm[32][160];
    const int* spot = which ? g_spot_pc : g_spot_im;
    int r0 = blockIdx.x*32;
    int tid = threadIdx.x;
    for (int i=tid; i<32*160; i+=256) ((unsigned*)bm)[i] = 0u;
    __syncthreads();
    for (int e=tid; e<32*125; e+=256){
        int row = e / 125;
        int v = spot[(size_t)(r0+row)*125 + (e % 125)];
        atomicOr(&bm[row][v>>5], 1u << (v & 31));
    }
    __syncthreads();
    if (tid < 32){
        int row = tid, t = 0;
        float* om = omask + (size_t)(r0+row)*125;
        float* oi = oidx  + (size_t)(r0+row)*125;
        for (int w2=0; w2<160; w2++){
            unsigned x = bm[row][w2];
            while (x){
                int b = __ffs(x) - 1; x &= x - 1;
                oi[t] = (float)(w2*32 + b); om[t] = 1.f; t++;
            }
        }
        for (int j=0; t<125; j++){
            if (!((bm[row][j>>5] >> (j&31)) & 1u)){
                oi[t] = (float)j; om[t] = 0.f; t++;
            }
        }
    }
}

// ---------------- launch ------------------------------------------------------
extern "C" void kernel_launch(void* const* d_in, const int* in_sizes, int n_in,
                              void* d_out, int out_size){
    const float* imf = (const float*)d_in[0];
    const float* pcf = (const float*)d_in[1];
    const float* pts = (const float*)d_in[2];
    float* out = (float*)d_out;

    float* sel_out     = out;                       // 25*5120
    float* mask_out    = out + 25*PP;               // 5120*125
    float* idx_out     = out + 25*PP + 125*PP;      // 5120*125
    float* idx_pc_out  = out + 25*PP + 2*125*PP;    // 5120*125
    float* mask_pc_out = out + 25*PP + 3*125*PP;    // 5120*125

    cudaFuncSetAttribute(k_gemm, cudaFuncAttributeMaxDynamicSharedMemorySize, 98304);

    // NOTE: launch order chosen so ncu's captured launch (4th) is k_gemm.
    k_norm<<<(PP*32 + 255)/256, 256>>>(imf, 0);            // 1
    k_norm<<<(PP*32 + 255)/256, 256>>>(pcf, 1);            // 2
    k_pack<<<PP/16 + PP/8, 256>>>();                       // 3
    k_gemm<<<dim3(PP/128, PP/128), 256, 98304>>>();        // 4  <- profiled
    k_knn<<<PP/KNN_WARPS, KNN_WARPS*32>>>(pts);            // 5
    k_unpack<<<(PP+255)/256, 256>>>();                     // 6
    k_impix<<<PP/4, 128>>>(sel_out);                       // 7
    k_pcpoint<<<PP/4, 128>>>();                            // 8
    k_mask<<<PP/32, 256>>>(0, mask_out, idx_out);          // 9
    k_mask<<<PP/32, 256>>>(1, mask_pc_out, idx_pc_out);    // 10
}

// round 12
// speedup vs baseline: 1.9174x; 1.3719x over previous
#include <cuda_runtime.h>

#define HH 40
#define WW 128
#define PP 5120
#define CC 128
#define KKN 25
#define SPOTN 5
#define NEGV (-1e8f)
#define FMAXV 3.402823466e38f
#define SENTK 0xffffffffffffffffull

// ---------------- scratch (device globals; no allocations allowed) ----------
__device__ float g_nimf[PP*CC];
__device__ float g_npcf[PP*CC];
__device__ float g_ahi[PP*CC];   // A fragments (imf) hi, mma-fragment layout
__device__ float g_alo[PP*CC];   // A fragments lo
__device__ float g_bhi[PP*CC];   // B fragments (pcf) hi
__device__ float g_blo[PP*CC];   // B fragments lo
__device__ float4 g_pts4[PP];    // padded points for vectorized knn
__device__ int   g_nb[PP*KKN];
__device__ unsigned long long g_rowbest[PP];
__device__ unsigned long long g_colbest[PP];
__device__ int   g_spot_im[PP*125];
__device__ int   g_spot_pc[PP*125];

__device__ __forceinline__ unsigned f2sort(float f){
    unsigned b = __float_as_uint(f);
    return (b & 0x80000000u) ? ~b : (b | 0x80000000u);
}
__device__ __forceinline__ float sort2f(unsigned u){
    unsigned b = (u & 0x80000000u) ? (u & 0x7fffffffu) : ~u;
    return __uint_as_float(b);
}
__device__ __forceinline__ int iclamp(int v, int lo, int hi){
    return v < lo ? lo : (v > hi ? hi : v);
}
__device__ __forceinline__ unsigned long long maxull(unsigned long long a, unsigned long long b){
    return a > b ? a : b;
}
__device__ __forceinline__ unsigned long long minull(unsigned long long a, unsigned long long b){
    return a < b ? a : b;
}
__device__ __forceinline__ float tf32r(float x){
    unsigned u; asm("cvt.rna.tf32.f32 %0, %1;" : "=r"(u) : "f"(x));
    return __uint_as_float(u);
}
__device__ __forceinline__ void cpasync16(unsigned s, const float* g){
    asm volatile("cp.async.cg.shared.global [%0], [%1], 16;\n" :: "r"(s), "l"(g));
}
#define KEYPACK(v,n) ((((unsigned long long)f2sort(v)) << 32) | (unsigned)(~(n)))

// ---------------- K1: L2 normalize both + argmax init ------------------------
__global__ __launch_bounds__(256) void k_norm(const float* __restrict__ imf,
                                              const float* __restrict__ pcf){
    int gt = blockIdx.x*blockDim.x + threadIdx.x;
    if (gt < PP){ g_rowbest[gt] = 0ull; g_colbest[gt] = 0ull; }
    int warp = gt >> 5;
    int lane = threadIdx.x & 31;
    if (warp >= 2*PP) return;
    const float* src = (warp < PP) ? imf : pcf;
    float* dst       = (warp < PP) ? g_nimf : g_npcf;
    int r = (warp < PP) ? warp : warp - PP;
    float4 v = ((const float4*)(src + (size_t)r*CC))[lane];
    float ss = v.x*v.x + v.y*v.y + v.z*v.z + v.w*v.w;
    #pragma unroll
    for (int o=16;o;o>>=1) ss += __shfl_xor_sync(0xffffffffu, ss, o);
    float inv = 1.0f / fmaxf(sqrtf(ss), 1e-12f);
    v.x*=inv; v.y*=inv; v.z*=inv; v.w*=inv;
    ((float4*)(dst + (size_t)r*CC))[lane] = v;
}

// ---------------- K2: tf32 hi/lo split into mma-fragment layout + pts4 -------
__global__ __launch_bounds__(256) void k_pack(const float* __restrict__ pts){
    int b = blockIdx.x;
    int tid = threadIdx.x;
    if (b < PP/16){
        int mt = b;
        #pragma unroll
        for (int s = tid; s < 512; s += 256){
            int kt = s >> 5, lane = s & 31;
            int g = lane >> 2, q = lane & 3;
            const float* base = g_nimf + (size_t)(mt*16)*CC + kt*8;
            float x0 = base[g*CC + q];
            float x1 = base[(g+8)*CC + q];
            float x2 = base[g*CC + q + 4];
            float x3 = base[(g+8)*CC + q + 4];
            float4 hi, lo;
            hi.x = tf32r(x0); lo.x = tf32r(x0 - hi.x);
            hi.y = tf32r(x1); lo.y = tf32r(x1 - hi.y);
            hi.z = tf32r(x2); lo.z = tf32r(x2 - hi.z);
            hi.w = tf32r(x3); lo.w = tf32r(x3 - hi.w);
            int o = (mt*16 + kt)*32 + lane;
            ((float4*)g_ahi)[o] = hi;
            ((float4*)g_alo)[o] = lo;
        }
    } else if (b < PP/16 + PP/8){
        int nt = b - PP/16;
        #pragma unroll
        for (int s = tid; s < 512; s += 256){
            int kt = s >> 5, lane = s & 31;
            int g = lane >> 2, q = lane & 3;
            const float* base = g_npcf + (size_t)(nt*8 + g)*CC + kt*8;
            float x0 = base[q], x1 = base[q+4];
            float2 hi, lo;
            hi.x = tf32r(x0); lo.x = tf32r(x0 - hi.x);
            hi.y = tf32r(x1); lo.y = tf32r(x1 - hi.y);
            int o = (nt*16 + kt)*32 + lane;
            ((float2*)g_bhi)[o] = hi;
            ((float2*)g_blo)[o] = lo;
        }
    } else {
        int i = (b - PP/16 - PP/8)*256 + tid;
        if (i < PP){
            float4 p; p.x = pts[3*i]; p.y = pts[3*i+1]; p.z = pts[3*i+2]; p.w = 0.f;
            g_pts4[i] = p;
        }
    }
}

// ---------------- K3: 3xTF32 GEMM, fragment-packed smem, 3-stage cp.async ---
__device__ __forceinline__ void mma_tf32(float& d0, float& d1, float& d2, float& d3,
    unsigned a0, unsigned a1, unsigned a2, unsigned a3, unsigned b0, unsigned b1){
    asm volatile("mma.sync.aligned.m16n8k8.row.col.f32.tf32.tf32.f32 "
        "{%0,%1,%2,%3},{%4,%5,%6,%7},{%8,%9},{%0,%1,%2,%3};\n"
        : "+f"(d0),"+f"(d1),"+f"(d2),"+f"(d3)
        : "r"(a0),"r"(a1),"r"(a2),"r"(a3),"r"(b0),"r"(b1));
}

#define STAGE_BYTES 32768u   // A 16KB (1024 float4) + B 16KB (2048 float2)
#define STAGE_FLOATS 8192

__device__ __forceinline__ void gemm_issue(unsigned sbase, int st, int c,
                                           int r0, int c0, int tid){
    const float* Ap = (c < 8) ? g_ahi : g_alo;             // hi,hi,lo
    const float* Bp = (c >= 4 && c < 8) ? g_blo : g_bhi;   // hi,lo,hi
    int kt0 = (c & 3)*4;
    int mt0 = r0 >> 4;
    int nt0 = c0 >> 3;
    unsigned abase = sbase + (unsigned)st*STAGE_BYTES;
    unsigned bbase = abase + 16384u;
    #pragma unroll
    for (int it=0; it<4; it++){
        int idx = it*256 + tid;
        int ga = (mt0 + (idx>>7))*512 + kt0*32 + (idx & 127);      // float4 units
        cpasync16(abase + idx*16, Ap + (size_t)ga*4);
        int gb = (nt0 + (idx>>6))*512 + kt0*32 + ((idx & 63)*2);   // float2 units
        cpasync16(bbase + idx*16, Bp + (size_t)gb*2);
    }
    asm volatile("cp.async.commit_group;\n");
}

__global__ __launch_bounds__(256,2) void k_gemm(){
    extern __shared__ __align__(16) float dynsmem[];
    unsigned sbase = (unsigned)__cvta_generic_to_shared(dynsmem);
    int tid = threadIdx.x;
    int lane = tid & 31;
    int warp = tid >> 5;
    int wm = warp >> 2, wn = warp & 3;
    int g = lane >> 2, q = lane & 3;
    int r0 = blockIdx.y*128, c0 = blockIdx.x*128;
    int mb = wm*64, nb = wn*32;

    float acc[4][4][4];
    #pragma unroll
    for (int a=0;a<4;a++)
        #pragma unroll
        for (int b=0;b<4;b++)
            #pragma unroll
            for (int i2=0;i2<4;i2++) acc[a][b][i2] = 0.f;

    gemm_issue(sbase, 0, 0, r0, c0, tid);
    gemm_issue(sbase, 1, 1, r0, c0, tid);
    gemm_issue(sbase, 2, 2, r0, c0, tid);

    #pragma unroll 1
    for (int c=0;c<12;c++){
        if (c <= 9)       asm volatile("cp.async.wait_group 2;\n");
        else if (c == 10) asm volatile("cp.async.wait_group 1;\n");
        else              asm volatile("cp.async.wait_group 0;\n");
        __syncthreads();
        const float4* sA = (const float4*)(dynsmem + (c % 3)*STAGE_FLOATS);
        const float2* sB = (const float2*)(dynsmem + (c % 3)*STAGE_FLOATS + 4096);
        #pragma unroll
        for (int ks=0; ks<4; ks++){
            float4 a4[4]; float2 b2[4];
            #pragma unroll
            for (int t=0;t<4;t++){
                a4[t] = sA[((wm*4 + t)*4 + ks)*32 + lane];
                b2[t] = sB[((wn*4 + t)*4 + ks)*32 + lane];
            }
            #pragma unroll
            for (int tm=0; tm<4; tm++)
                #pragma unroll
                for (int tn=0; tn<4; tn++)
                    mma_tf32(acc[tm][tn][0], acc[tm][tn][1], acc[tm][tn][2], acc[tm][tn][3],
                             __float_as_uint(a4[tm].x), __float_as_uint(a4[tm].y),
                             __float_as_uint(a4[tm].z), __float_as_uint(a4[tm].w),
                             __float_as_uint(b2[tn].x), __float_as_uint(b2[tn].y));
        }
        __syncthreads();
        if (c <= 8) gemm_issue(sbase, c % 3, c + 3, r0, c0, tid);
    }

    // ---- epilogue: packed row/col argmax via shared u64 atomics ----
    unsigned long long* rowk = (unsigned long long*)dynsmem;     // 128
    unsigned long long* colk = rowk + 128;                       // 128
    if (tid < 128){ rowk[tid] = 0ull; colk[tid] = 0ull; }
    __syncthreads();

    #pragma unroll
    for (int tm=0; tm<4; tm++){
        unsigned long long klo = 0ull, khi = 0ull;
        #pragma unroll
        for (int tn=0; tn<4; tn++){
            int n0 = c0 + nb + tn*8 + 2*q;
            klo = maxull(klo, KEYPACK(acc[tm][tn][0], n0));
            klo = maxull(klo, KEYPACK(acc[tm][tn][1], n0+1));
            khi = maxull(khi, KEYPACK(acc[tm][tn][2], n0));
            khi = maxull(khi, KEYPACK(acc[tm][tn][3], n0+1));
        }
        atomicMax(&rowk[mb + tm*16 + g    ], klo);
        atomicMax(&rowk[mb + tm*16 + g + 8], khi);
    }
    #pragma unroll
    for (int tn=0; tn<4; tn++){
        unsigned long long c0k = 0ull, c1k = 0ull;
        #pragma unroll
        for (int tm=0; tm<4; tm++){
            int m0 = r0 + mb + tm*16 + g;
            c0k = maxull(c0k, KEYPACK(acc[tm][tn][0], m0));
            c0k = maxull(c0k, KEYPACK(acc[tm][tn][2], m0+8));
            c1k = maxull(c1k, KEYPACK(acc[tm][tn][1], m0));
            c1k = maxull(c1k, KEYPACK(acc[tm][tn][3], m0+8));
        }
        atomicMax(&colk[nb + tn*8 + 2*q    ], c0k);
        atomicMax(&colk[nb + tn*8 + 2*q + 1], c1k);
    }
    __syncthreads();
    if (tid < 128) atomicMax(&g_rowbest[r0+tid], rowk[tid]);
    else           atomicMax(&g_colbest[c0+tid-128], colk[tid-128]);
}

// ---------------- K4: knn, warp-per-row, per-lane top-4 caches, LDG.128 -----
#define KNN_WARPS 8
__global__ __launch_bounds__(KNN_WARPS*32) void k_knn(){
    int warp = threadIdx.x >> 5;
    int lane = threadIdx.x & 31;
    int i = blockIdx.x*KNN_WARPS + warp;
    float4 cp = g_pts4[i];
    float px = cp.x, py = cp.y, pz = cp.z;

    unsigned long long k0=SENTK,k1=SENTK,k2=SENTK,k3=SENTK;
    for (int j=lane; j<PP; j+=32){
        float4 pv = g_pts4[j];
        float dx = pv.x-px, dy = pv.y-py, dz = pv.z-pz;
        float d2 = fmaf(dx,dx, fmaf(dy,dy, dz*dz));
        unsigned long long key = ((unsigned long long)__float_as_uint(d2) << 32) | (unsigned)j;
        if (key < k3){
            k3 = key;
            if (k3 < k2){ unsigned long long t=k2; k2=k3; k3=t; }
            if (k2 < k1){ unsigned long long t=k1; k1=k2; k2=t; }
            if (k1 < k0){ unsigned long long t=k0; k0=k1; k1=t; }
        }
    }

    #pragma unroll 1
    for (int t=0; t<KKN; t++){
        unsigned long long m = k0;
        #pragma unroll
        for (int o=16;o;o>>=1) m = minull(m, __shfl_xor_sync(0xffffffffu, m, o));
        unsigned own = __ballot_sync(0xffffffffu, k0 == m);
        if (lane == 0) g_nb[i*KKN + t] = (int)(unsigned)m;
        if (own & (1u << lane)){
            k0 = k1; k1 = k2; k2 = k3; k3 = SENTK;
            if (k0 == SENTK){
                #pragma unroll 1
                for (int j=lane; j<PP; j+=32){
                    float4 pv = g_pts4[j];
                    float dx = pv.x-px, dy = pv.y-py, dz = pv.z-pz;
                    float d2 = fmaf(dx,dx, fmaf(dy,dy, dz*dz));
                    unsigned long long key = ((unsigned long long)__float_as_uint(d2) << 32) | (unsigned)j;
                    if (key > m && key < k3){
                        k3 = key;
                        if (k3 < k2){ unsigned long long q=k2; k2=k3; k3=q; }
                        if (k2 < k1){ unsigned long long q=k1; k1=k2; k2=q; }
                        if (k1 < k0){ unsigned long long q=k0; k0=k1; k1=q; }
                    }
                }
            }
        }
    }
}

// ---------------- K5: merged im/pc branch (warp per row) ---------------------
// global warp id < PP: im pixel branch; else pc point branch (row - PP).
__global__ __launch_bounds__(128) void k_spot(float* __restrict__ sel_out){
    int gwarp = (blockIdx.x*blockDim.x + threadIdx.x) >> 5;
    int lane = threadIdx.x & 31;
    if (gwarp < PP){
        int p = gwarp, h = p >> 7, w = p & 127;   // WW == 128
        float4 cf = ((const float4*)(g_nimf + (size_t)p*CC))[lane];
        float acc[KKN];
        #pragma unroll
        for (int k=0; k<KKN; k++){
            int di = k/5 - 2, dj = k%5 - 2;
            int hh = iclamp(h+di, 0, HH-1), ww = iclamp(w+dj, 0, WW-1);
            float4 nf = ((const float4*)(g_nimf + (size_t)(hh*WW+ww)*CC))[lane];
            acc[k] = fmaf(cf.x,nf.x, fmaf(cf.y,nf.y, fmaf(cf.z,nf.z, cf.w*nf.w)));
        }
        #pragma unroll
        for (int o=16;o;o>>=1){
            #pragma unroll
            for (int k=0; k<KKN; k++) acc[k] += __shfl_xor_sync(0xffffffffu, acc[k], o);
        }
        float v = -FMAXV;
        #pragma unroll
        for (int k=0; k<KKN; k++) if (lane == k) v = acc[k];

        float m = v;
        #pragma unroll
        for (int o=16;o;o>>=1) m = fmaxf(m, __shfl_xor_sync(0xffffffffu, m, o));
        float e = (lane < KKN) ? expf(v - m) : 0.f;
        float su = e;
        #pragma unroll
        for (int o=16;o;o>>=1) su += __shfl_xor_sync(0xffffffffu, su, o);
        float soft = e / su;

        int di = lane/5 - 2, dj = lane%5 - 2;
        float selv = NEGV;
        if (lane < KKN){
            bool inb = ((unsigned)(h+di) < (unsigned)HH) && ((unsigned)(w+dj) < (unsigned)WW);
            int hh = iclamp(h+di, 0, HH-1), ww = iclamp(w+dj, 0, WW-1);
            float conf = sort2f((unsigned)(g_rowbest[hh*WW+ww] >> 32));
            selv = inb ? soft*conf : NEGV;
            sel_out[(size_t)lane*PP + p] = selv;
        }
        float cand = (lane < KKN && lane != 12) ? selv : -FMAXV;
        #pragma unroll 1
        for (int s=0; s<SPOTN; s++){
            int kk;
            if (s == 0){
                kk = 12;
            } else {
                unsigned long long key = ((unsigned long long)f2sort(cand) << 32) | (unsigned)(31 - lane);
                #pragma unroll
                for (int o=16;o;o>>=1){
                    unsigned long long ok = __shfl_xor_sync(0xffffffffu, key, o);
                    if (ok > key) key = ok;
                }
                kk = 31 - (int)(key & 0xffffffffull);
                if (lane == kk) cand = -FMAXV;
            }
            int q = (h + kk/5 - 2)*WW + (w + kk%5 - 2);
            int sd = (int)(~(unsigned)g_rowbest[q]);
            if (lane < KKN) g_spot_im[(size_t)p*125 + s*25 + lane] = g_nb[sd*KKN + lane];
        }
    } else {
        int p = gwarp - PP;
        float4 cf = ((const float4*)(g_npcf + (size_t)p*CC))[lane];
        int nbk[KKN];
        #pragma unroll
        for (int k=0; k<KKN; k++) nbk[k] = g_nb[p*KKN + k];
        float acc[KKN];
        #pragma unroll
        for (int k=0; k<KKN; k++){
            float4 nf = ((const float4*)(g_npcf + (size_t)nbk[k]*CC))[lane];
            acc[k] = fmaf(cf.x,nf.x, fmaf(cf.y,nf.y, fmaf(cf.z,nf.z, cf.w*nf.w)));
        }
        #pragma unroll
        for (int o=16;o;o>>=1){
            #pragma unroll
            for (int k=0; k<KKN; k++) acc[k] += __shfl_xor_sync(0xffffffffu, acc[k], o);
        }
        float v = -FMAXV; int myq = 0;
        #pragma unroll
        for (int k=0; k<KKN; k++) if (lane == k){ v = acc[k]; myq = nbk[k]; }

        float m = v;
        #pragma unroll
        for (int o=16;o;o>>=1) m = fmaxf(m, __shfl_xor_sync(0xffffffffu, m, o));
        float e = (lane < KKN) ? expf(v - m) : 0.f;
        float su = e;
        #pragma unroll
        for (int o=16;o;o>>=1) su += __shfl_xor_sync(0xffffffffu, su, o);
        float soft = e / su;

        float selv = NEGV;
        if (lane < KKN && lane != 0)
            selv = soft * sort2f((unsigned)(g_colbest[myq] >> 32));
        float cand = (lane >= 1 && lane < KKN) ? selv : -FMAXV;
        #pragma unroll 1
        for (int s=0; s<SPOTN; s++){
            int kk;
            if (s == 0){
                kk = 0;
            } else {
                unsigned long long key = ((unsigned long long)f2sort(cand) << 32) | (unsigned)(31 - lane);
                #pragma unroll
                for (int o=16;o;o>>=1){
                    unsigned long long ok = __shfl_xor_sync(0xffffffffu, key, o);
                    if (ok > key) key = ok;
                }
                kk = 31 - (int)(key & 0xffffffffull);
                if (lane == kk) cand = -FMAXV;
            }
            int qq = __shfl_sync(0xffffffffu, myq, kk);
            int pix = (int)(~(unsigned)g_colbest[qq]);
            int pr = pix >> 7, pc = pix & 127;
            if (lane < KKN){
                int rr = iclamp(pr + lane/5 - 2, 0, HH-1);
                int cc = iclamp(pc + lane%5 - 2, 0, WW-1);
                g_spot_pc[(size_t)p*125 + s*25 + lane] = rr*WW + cc;
            }
        }
    }
}

// ---------------- K6: scatter mask + stable top-125, warp per row ------------
// grid (PP/8, 2): blockIdx.y 0 -> im outputs, 1 -> pc outputs.
__global__ __launch_bounds__(256) void k_mask(float* __restrict__ mask_im,
                                              float* __restrict__ idx_im,
                                              float* __restrict__ idx_pc,
                                              float* __restrict__ mask_pc){
    __shared__ unsigned bm[8][160];
    int which = blockIdx.y;
    const int* spot = which ? g_spot_pc : g_spot_im;
    float* omask = which ? mask_pc : mask_im;
    float* oidx  = which ? idx_pc  : idx_im;
    int wid  = threadIdx.x >> 5;
    int lane = threadIdx.x & 31;
    int row = blockIdx.x*8 + wid;

    #pragma unroll
    for (int w=0; w<5; w++) bm[wid][lane*5 + w] = 0u;
    __syncwarp();
    for (int i=lane; i<125; i+=32){
        int v = spot[(size_t)row*125 + i];
        atomicOr(&bm[wid][v>>5], 1u << (v & 31));
    }
    __syncwarp();

    unsigned wds[5]; int cnt = 0;
    #pragma unroll
    for (int w=0; w<5; w++){ wds[w] = bm[wid][lane*5 + w]; cnt += __popc(wds[w]); }
    // warp inclusive prefix sum of cnt
    int incl = cnt;
    #pragma unroll
    for (int o=1;o<32;o<<=1){
        int t = __shfl_up_sync(0xffffffffu, incl, o);
        if (lane >= o) incl += t;
    }
    int excl = incl - cnt;
    int total = __shfl_sync(0xffffffffu, incl, 31);

    float* om = omask + (size_t)row*125;
    float* oi = oidx  + (size_t)row*125;
    // present entries (ascending): lane covers j in [160*lane, 160*lane+160)
    int slot = excl;
    #pragma unroll
    for (int w=0; w<5; w++){
        unsigned x = wds[w];
        int base = (lane*5 + w)*32;
        while (x){
            int b = __ffs(x) - 1; x &= x - 1;
            oi[slot] = (float)(base + b); om[slot] = 1.f; slot++;
        }
    }
    // absent fill (ascending) up to 125 total
    int arank = 160*lane - excl;        // absent count before this segment
    slot = total + arank;
    if (slot < 125){
        #pragma unroll
        for (int w=0; w<5 && slot < 125; w++){
            unsigned y = ~wds[w];
            int base = (lane*5 + w)*32;
            while (y && slot < 125){
                int b = __ffs(y) - 1; y &= y - 1;
                oi[slot] = (float)(base + b); om[slot] = 0.f; slot++;
            }
        }
    }
}

// ---------------- launch ------------------------------------------------------
extern "C" void kernel_launch(void* const* d_in, const int* in_sizes, int n_in,
                              void* d_out, int out_size){
    const float* imf = (const float*)d_in[0];
    const float* pcf = (const float*)d_in[1];
    const float* pts = (const float*)d_in[2];
    float* out = (float*)d_out;

    float* sel_out     = out;                       // 25*5120
    float* mask_out    = out + 25*PP;               // 5120*125
    float* idx_out     = out + 25*PP + 125*PP;      // 5120*125
    float* idx_pc_out  = out + 25*PP + 2*125*PP;    // 5120*125
    float* mask_pc_out = out + 25*PP + 3*125*PP;    // 5120*125

    cudaFuncSetAttribute(k_gemm, cudaFuncAttributeMaxDynamicSharedMemorySize, 98304);

    // NOTE: launch order chosen so ncu's captured launch (4th) is k_knn.
    k_norm<<<(2*PP*32 + 255)/256, 256>>>(imf, pcf);                   // 1
    k_pack<<<PP/16 + PP/8 + (PP+255)/256, 256>>>(pts);                // 2
    k_gemm<<<dim3(PP/128, PP/128), 256, 98304>>>();                   // 3
    k_knn<<<PP/KNN_WARPS, KNN_WARPS*32>>>();                          // 4 <- profiled
    k_spot<<<2*PP/4, 128>>>(sel_out);                                 // 5
    k_mask<<<dim3(PP/8, 2), 256>>>(mask_out, idx_out, idx_pc_out, mask_pc_out); // 6
}